// round 1
// baseline (speedup 1.0000x reference)
#include <cuda_runtime.h>
#include <math.h>

#define KDIM   768
#define HEADS  8
#define KH     6144
#define TSEQ   1024
#define NBATCH 2
#define BT     2048
#define VOCAB  32000
#define FFD    3072

// ---------------- scratch (device globals; no runtime allocation) ----------
__device__ float g_xe[BT * KDIM];
__device__ float g_q [BT * KH];
__device__ float g_k [BT * KH];
__device__ float g_v [BT * KH];
__device__ float g_s [(size_t)NBATCH * HEADS * TSEQ * TSEQ];  // 64 MB
__device__ float g_y [BT * KH];
__device__ float g_t1[BT * KDIM];
__device__ float g_t2[BT * KDIM];
__device__ float g_ff[BT * FFD];

// ---------------- generic SGEMM: 128x128 tile, BK=8, 256 thr, 8x8/thr ------
// EPI: 0 = none, 1 = scale, 2 = +bias, 3 = +bias then exact GELU
// TB : false -> C = A(MxK) * B(KxN);  true -> C = A(MxK) * B(NxK)^T
template <int EPI, bool TB>
__global__ void __launch_bounds__(256) gemm_k(
    const float* __restrict__ A, const float* __restrict__ Bm,
    float* __restrict__ C, const float* __restrict__ bias,
    int M, int N, int Kd, int lda, int ldb, int ldc,
    long long zAb, long long zAh, long long zBb, long long zBh,
    long long zCb, long long zCh, int Hn, float scale)
{
    __shared__ float As[8][128];
    __shared__ float Bs[8][128];

    const int tid = threadIdx.x;
    const int bx = blockIdx.x, by = blockIdx.y, bz = blockIdx.z;
    {
        const int zb = bz / Hn, zh = bz % Hn;
        A  += zb * zAb + zh * zAh;
        Bm += zb * zBb + zh * zBh;
        C  += zb * zCb + zh * zCh;
    }
    const int tx = tid & 15, ty = tid >> 4;

    // tile-load lanes
    const int arow = tid >> 1;            // 0..127
    const int ac4  = (tid & 1) * 4;       // 0 or 4 (k offset)
    const int bkr  = tid >> 5;            // 0..7
    const int bcol = (tid & 31) * 4;      // 0..124

    const float* Ap = A + (size_t)(by * 128 + arow) * lda + ac4;
    const float* Bp = TB ? (Bm + (size_t)(bx * 128 + arow) * ldb + ac4)
                         : (Bm + (size_t)bkr * ldb + bx * 128 + bcol);

    float acc[8][8];
#pragma unroll
    for (int i = 0; i < 8; i++)
#pragma unroll
        for (int j = 0; j < 8; j++) acc[i][j] = 0.f;

    for (int k0 = 0; k0 < Kd; k0 += 8) {
        float4 a4 = *(const float4*)(Ap + k0);
        As[ac4 + 0][arow] = a4.x; As[ac4 + 1][arow] = a4.y;
        As[ac4 + 2][arow] = a4.z; As[ac4 + 3][arow] = a4.w;
        if (TB) {
            float4 b4 = *(const float4*)(Bp + k0);
            Bs[ac4 + 0][arow] = b4.x; Bs[ac4 + 1][arow] = b4.y;
            Bs[ac4 + 2][arow] = b4.z; Bs[ac4 + 3][arow] = b4.w;
        } else {
            *(float4*)&Bs[bkr][bcol] = *(const float4*)(Bp + (size_t)k0 * ldb);
        }
        __syncthreads();
#pragma unroll
        for (int kk = 0; kk < 8; kk++) {
            float4 a0 = *(const float4*)&As[kk][ty * 4];
            float4 a1 = *(const float4*)&As[kk][ty * 4 + 64];
            float4 b0 = *(const float4*)&Bs[kk][tx * 4];
            float4 b1 = *(const float4*)&Bs[kk][tx * 4 + 64];
            float ar[8] = {a0.x, a0.y, a0.z, a0.w, a1.x, a1.y, a1.z, a1.w};
            float br[8] = {b0.x, b0.y, b0.z, b0.w, b1.x, b1.y, b1.z, b1.w};
#pragma unroll
            for (int i = 0; i < 8; i++)
#pragma unroll
                for (int j = 0; j < 8; j++)
                    acc[i][j] = fmaf(ar[i], br[j], acc[i][j]);
        }
        __syncthreads();
    }

#pragma unroll
    for (int ii = 0; ii < 2; ii++) {
#pragma unroll
        for (int i = 0; i < 4; i++) {
            const int row = by * 128 + ty * 4 + ii * 64 + i;
#pragma unroll
            for (int jj = 0; jj < 2; jj++) {
                const int col = bx * 128 + tx * 4 + jj * 64;
                float r[4];
#pragma unroll
                for (int j = 0; j < 4; j++) r[j] = acc[ii * 4 + i][jj * 4 + j];
                if (EPI == 1) {
#pragma unroll
                    for (int j = 0; j < 4; j++) r[j] *= scale;
                } else if (EPI >= 2) {
#pragma unroll
                    for (int j = 0; j < 4; j++) r[j] += bias[col + j];
                    if (EPI == 3) {
#pragma unroll
                        for (int j = 0; j < 4; j++)
                            r[j] = 0.5f * r[j] * (1.0f + erff(r[j] * 0.7071067811865476f));
                    }
                }
                float4 o = make_float4(r[0], r[1], r[2], r[3]);
                *(float4*)(C + (size_t)row * ldc + col) = o;
            }
        }
    }
}

// ---------------- embedding + sinusoidal positional encoding ---------------
__global__ void embed_k(const int* __restrict__ x, const float* __restrict__ emb,
                        float* __restrict__ xe)
{
    const int row = blockIdx.x;            // 0..BT-1
    const int t = row & (TSEQ - 1);
    const int tok = x[row];
    const float* e = emb + (size_t)tok * KDIM;
    for (int c = threadIdx.x; c < KDIM; c += blockDim.x) {
        const int j = c >> 1;
        const float expo = (2.0f * (float)(2 * j)) / (float)KDIM;
        const float div = powf(10000.0f, expo);
        const float ang = (float)t / div;
        const float pe = (c & 1) ? cosf(ang) : sinf(ang);
        xe[(size_t)row * KDIM + c] = e[c] + pe;
    }
}

// ---------------- row softmax over T=1024 (256 thr, 4 elems/thr) -----------
__global__ void __launch_bounds__(256) softmax_k(float* __restrict__ s)
{
    float* p = s + (size_t)blockIdx.x * TSEQ;
    const int tid = threadIdx.x;
    __shared__ float sh[8];

    float v[4];
    float m = -3.4e38f;
#pragma unroll
    for (int i = 0; i < 4; i++) { v[i] = p[tid + i * 256]; m = fmaxf(m, v[i]); }
#pragma unroll
    for (int o = 16; o > 0; o >>= 1) m = fmaxf(m, __shfl_xor_sync(0xffffffffu, m, o));
    if ((tid & 31) == 0) sh[tid >> 5] = m;
    __syncthreads();
    m = fmaxf(fmaxf(fmaxf(sh[0], sh[1]), fmaxf(sh[2], sh[3])),
              fmaxf(fmaxf(sh[4], sh[5]), fmaxf(sh[6], sh[7])));
    __syncthreads();

    float sum = 0.f;
#pragma unroll
    for (int i = 0; i < 4; i++) { v[i] = expf(v[i] - m); sum += v[i]; }
#pragma unroll
    for (int o = 16; o > 0; o >>= 1) sum += __shfl_xor_sync(0xffffffffu, sum, o);
    if ((tid & 31) == 0) sh[tid >> 5] = sum;
    __syncthreads();
    sum = sh[0] + sh[1] + sh[2] + sh[3] + sh[4] + sh[5] + sh[6] + sh[7];
    const float inv = 1.0f / sum;
#pragma unroll
    for (int i = 0; i < 4; i++) p[tid + i * 256] = v[i] * inv;
}

// ---------------- layernorm over K=768 (256 thr, 3 elems/thr) --------------
__global__ void __launch_bounds__(256) ln_k(const float* __restrict__ in,
                                            float* __restrict__ out,
                                            const float* __restrict__ gw,
                                            const float* __restrict__ bw)
{
    const float* p = in + (size_t)blockIdx.x * KDIM;
    float* o = out + (size_t)blockIdx.x * KDIM;
    const int tid = threadIdx.x;
    __shared__ float sh[8];

    float v[3];
    float s = 0.f;
#pragma unroll
    for (int i = 0; i < 3; i++) { v[i] = p[tid + i * 256]; s += v[i]; }
#pragma unroll
    for (int off = 16; off > 0; off >>= 1) s += __shfl_xor_sync(0xffffffffu, s, off);
    if ((tid & 31) == 0) sh[tid >> 5] = s;
    __syncthreads();
    const float mu = (sh[0] + sh[1] + sh[2] + sh[3] + sh[4] + sh[5] + sh[6] + sh[7])
                     * (1.0f / (float)KDIM);
    __syncthreads();

    float vs = 0.f;
#pragma unroll
    for (int i = 0; i < 3; i++) { const float d = v[i] - mu; vs += d * d; }
#pragma unroll
    for (int off = 16; off > 0; off >>= 1) vs += __shfl_xor_sync(0xffffffffu, vs, off);
    if ((tid & 31) == 0) sh[tid >> 5] = vs;
    __syncthreads();
    const float var = (sh[0] + sh[1] + sh[2] + sh[3] + sh[4] + sh[5] + sh[6] + sh[7])
                      * (1.0f / (float)KDIM);
    const float inv = rsqrtf(var + 1e-5f);
#pragma unroll
    for (int i = 0; i < 3; i++) {
        const int c = tid + i * 256;
        o[c] = (v[i] - mu) * inv * gw[c] + bw[c];
    }
}

// ---------------- host-side GEMM dispatch -----------------------------------
static inline void run_gemm(int epi, bool tb,
                            const float* A, const float* B, float* C, const float* bias,
                            int M, int N, int Kd, int lda, int ldb, int ldc,
                            long long zAb, long long zAh, long long zBb, long long zBh,
                            long long zCb, long long zCh, int Z, int Hn, float scale)
{
    dim3 g(N / 128, M / 128, Z), b(256);
    if (tb) {
        gemm_k<1, true><<<g, b>>>(A, B, C, bias, M, N, Kd, lda, ldb, ldc,
                                  zAb, zAh, zBb, zBh, zCb, zCh, Hn, scale);
    } else if (epi == 0) {
        gemm_k<0, false><<<g, b>>>(A, B, C, bias, M, N, Kd, lda, ldb, ldc,
                                   zAb, zAh, zBb, zBh, zCb, zCh, Hn, scale);
    } else if (epi == 2) {
        gemm_k<2, false><<<g, b>>>(A, B, C, bias, M, N, Kd, lda, ldb, ldc,
                                   zAb, zAh, zBb, zBh, zCb, zCh, Hn, scale);
    } else {
        gemm_k<3, false><<<g, b>>>(A, B, C, bias, M, N, Kd, lda, ldb, ldc,
                                   zAb, zAh, zBb, zBh, zCb, zCh, Hn, scale);
    }
}

extern "C" void kernel_launch(void* const* d_in, const int* in_sizes, int n_in,
                              void* d_out, int out_size)
{
    const int*   x    = (const int*)  d_in[0];
    const float* emb  = (const float*)d_in[1];
    const float* Wq   = (const float*)d_in[2];
    const float* Wk   = (const float*)d_in[3];
    const float* Wv   = (const float*)d_in[4];
    const float* Wu   = (const float*)d_in[5];
    const float* bu   = (const float*)d_in[6];
    const float* ln1g = (const float*)d_in[7];
    const float* ln1b = (const float*)d_in[8];
    const float* Wf1  = (const float*)d_in[9];
    const float* bf1  = (const float*)d_in[10];
    const float* Wf2  = (const float*)d_in[11];
    const float* bf2  = (const float*)d_in[12];
    const float* ln2g = (const float*)d_in[13];
    const float* ln2b = (const float*)d_in[14];
    const float* lnfg = (const float*)d_in[15];
    const float* lnfb = (const float*)d_in[16];
    const float* Wout = (const float*)d_in[17];
    const float* bout = (const float*)d_in[18];
    float* out = (float*)d_out;

    float *xe, *q, *k, *v, *sc, *y, *t1, *t2, *ff;
    cudaGetSymbolAddress((void**)&xe, g_xe);
    cudaGetSymbolAddress((void**)&q,  g_q);
    cudaGetSymbolAddress((void**)&k,  g_k);
    cudaGetSymbolAddress((void**)&v,  g_v);
    cudaGetSymbolAddress((void**)&sc, g_s);
    cudaGetSymbolAddress((void**)&y,  g_y);
    cudaGetSymbolAddress((void**)&t1, g_t1);
    cudaGetSymbolAddress((void**)&t2, g_t2);
    cudaGetSymbolAddress((void**)&ff, g_ff);

    const float scale = 1.0f / sqrtf((float)KDIM);

    embed_k<<<BT, 256>>>(x, emb, xe);

    for (int l = 0; l < 2; l++) {
        const float* wq = Wq + (size_t)l * KDIM * KH;
        const float* wk = Wk + (size_t)l * KDIM * KH;
        const float* wv = Wv + (size_t)l * KDIM * KH;
        const float* wu = Wu + (size_t)l * KH * KDIM;

        // QKV projections: [2048,768] x [768,6144]
        run_gemm(0, false, xe, wq, q, nullptr, BT, KH, KDIM, KDIM, KH, KH,
                 0, 0, 0, 0, 0, 0, 1, 1, 0.f);
        run_gemm(0, false, xe, wk, k, nullptr, BT, KH, KDIM, KDIM, KH, KH,
                 0, 0, 0, 0, 0, 0, 1, 1, 0.f);
        run_gemm(0, false, xe, wv, v, nullptr, BT, KH, KDIM, KDIM, KH, KH,
                 0, 0, 0, 0, 0, 0, 1, 1, 0.f);

        // scores[b,h] = Q_h K_h^T * scale : batched over z = b*H + h
        run_gemm(1, true, q, k, sc, nullptr, TSEQ, TSEQ, KDIM, KH, KH, TSEQ,
                 (long long)TSEQ * KH, KDIM,
                 (long long)TSEQ * KH, KDIM,
                 (long long)HEADS * TSEQ * TSEQ, (long long)TSEQ * TSEQ,
                 NBATCH * HEADS, HEADS, scale);

        softmax_k<<<NBATCH * HEADS * TSEQ, 256>>>(sc);

        // y[b,:,h,:] = P_h @ V_h
        run_gemm(0, false, sc, v, y, nullptr, TSEQ, KDIM, TSEQ, TSEQ, KH, KH,
                 (long long)HEADS * TSEQ * TSEQ, (long long)TSEQ * TSEQ,
                 (long long)TSEQ * KH, KDIM,
                 (long long)TSEQ * KH, KDIM,
                 NBATCH * HEADS, HEADS, 0.f);

        // att = y @ Wu + bu
        run_gemm(2, false, y, wu, t1, bu + l * KDIM, BT, KDIM, KH, KH, KDIM, KDIM,
                 0, 0, 0, 0, 0, 0, 1, 1, 0.f);
        ln_k<<<BT, 256>>>(t1, t2, ln1g + l * KDIM, ln1b + l * KDIM);

        // FFN
        run_gemm(3, false, t2, Wf1 + (size_t)l * KDIM * FFD, ff, bf1 + l * FFD,
                 BT, FFD, KDIM, KDIM, FFD, FFD, 0, 0, 0, 0, 0, 0, 1, 1, 0.f);
        run_gemm(2, false, ff, Wf2 + (size_t)l * FFD * KDIM, t1, bf2 + l * KDIM,
                 BT, KDIM, FFD, FFD, KDIM, KDIM, 0, 0, 0, 0, 0, 0, 1, 1, 0.f);
        ln_k<<<BT, 256>>>(t1, xe, ln2g + l * KDIM, ln2b + l * KDIM);
    }

    ln_k<<<BT, 256>>>(xe, t2, lnfg, lnfb);

    // logits = xf @ Wout + bout : [2048,768] x [768,32000]
    run_gemm(2, false, t2, Wout, out, bout, BT, VOCAB, KDIM, KDIM, VOCAB, VOCAB,
             0, 0, 0, 0, 0, 0, 1, 1, 0.f);
}

// round 3
// speedup vs baseline: 1.2683x; 1.2683x over previous
#include <cuda_runtime.h>
#include <math.h>
#include <stdint.h>

#define KDIM   768
#define HEADS  8
#define KH     6144
#define TSEQ   1024
#define NBATCH 2
#define BT     2048
#define VOCAB  32000
#define FFD    3072

// ---------------- scratch (device globals; no runtime allocation) ----------
__device__ float g_xe[BT * KDIM];
__device__ float g_q [BT * KH];
__device__ float g_k [BT * KH];
__device__ float g_v [BT * KH];
__device__ float g_s [(size_t)NBATCH * HEADS * TSEQ * TSEQ];  // 64 MB
__device__ float g_y [BT * KH];
__device__ float g_t1[BT * KDIM];
__device__ float g_t2[BT * KDIM];
__device__ float g_ff[BT * FFD];

// ---------------- helpers ----------------------------------------------------
__device__ __forceinline__ float f2tf(float f) {
    uint32_t r; asm("cvt.rna.tf32.f32 %0, %1;" : "=r"(r) : "f"(f));
    return __uint_as_float(r);
}
__device__ __forceinline__ void mma1688(float c[4],
                                        float a0, float a1, float a2, float a3,
                                        float b0, float b1) {
    asm volatile(
        "mma.sync.aligned.m16n8k8.row.col.f32.tf32.tf32.f32 "
        "{%0,%1,%2,%3}, {%4,%5,%6,%7}, {%8,%9}, {%0,%1,%2,%3};"
        : "+f"(c[0]), "+f"(c[1]), "+f"(c[2]), "+f"(c[3])
        : "r"(__float_as_uint(a0)), "r"(__float_as_uint(a1)),
          "r"(__float_as_uint(a2)), "r"(__float_as_uint(a3)),
          "r"(__float_as_uint(b0)), "r"(__float_as_uint(b1)));
}

// ---------------- tf32 tensor GEMM -------------------------------------------
// C[M,N] = A[M,K] @ B, smem B staged as [k][n].
//   TRANS=false: gmem B is [N,K] row-major (QK^T: B = K matrix)
//   TRANS=true : gmem B is [K,N] row-major (weights, V)
// EPI: 0 none, 1 *scale, 2 +bias, 3 +bias + exact GELU
// Block tile 128x128, BK=32, 256 threads (8 warps: 2 M x 4 N), warp tile 64x32.
#define KSTR 136                       // padded m/n stride (floats) in smem
#define ABUF (32 * KSTR)               // 4352 floats per A (or B) stage
#define SMEM_MMA (4 * ABUF * 4)        // 69632 bytes (2 stages x (A+B))

template <int EPI, bool TRANS>
__global__ void __launch_bounds__(256) gemm_mma(
    const float* __restrict__ A, const float* __restrict__ B,
    float* __restrict__ C, const float* __restrict__ bias,
    int Kd, int lda, int ldb, int ldc,
    long long zAb, long long zAh, long long zBb, long long zBh,
    long long zCb, long long zCh, int Hn, float scale)
{
    extern __shared__ float sm[];   // [A0 | B0 | A1 | B1], each ABUF floats

    const int tid = threadIdx.x;
    const int lane = tid & 31, wid = tid >> 5;
    const int g = lane >> 2, tig = lane & 3;
    const int wm = (wid & 1) * 64, wn = (wid >> 1) * 32;
    const int bx = blockIdx.x, by = blockIdx.y, bz = blockIdx.z;
    {
        const int zb = bz / Hn, zh = bz % Hn;
        A += (size_t)zb * zAb + (size_t)zh * zAh;
        B += (size_t)zb * zBb + (size_t)zh * zBh;
        C += (size_t)zb * zCb + (size_t)zh * zCh;
    }

    // staging lanes
    const int rowA = tid >> 1, kcA = (tid & 1) * 16;     // A: [M,K] coalesced k
    const float* Abase = A + (size_t)(by * 128 + rowA) * lda + kcA;
    // B TRANS=true : [K,N] -> row k = tid>>3, n chunk (tid&7)*16
    const int kB = tid >> 3, nB = (tid & 7) * 16;
    // B TRANS=false: [N,K] -> row n = tid>>1, k chunk (tid&1)*16
    const int nB2 = tid >> 1, kcB = (tid & 1) * 16;
    const float* Bbase = TRANS ? (B + (size_t)kB * ldb + bx * 128 + nB)
                               : (B + (size_t)(bx * 128 + nB2) * ldb + kcB);

    float acc[4][4][4];
#pragma unroll
    for (int i = 0; i < 4; i++)
#pragma unroll
        for (int j = 0; j < 4; j++)
#pragma unroll
            for (int c = 0; c < 4; c++) acc[i][j][c] = 0.f;

    const int NT = Kd >> 5;
    float4 ra[4], rb[4];

    // ---- prologue: stage tile 0 ----
#pragma unroll
    for (int i = 0; i < 4; i++) ra[i] = *(const float4*)(Abase + i * 4);
    if (TRANS) {
#pragma unroll
        for (int i = 0; i < 4; i++) rb[i] = *(const float4*)(Bbase + i * 4);
    } else {
#pragma unroll
        for (int i = 0; i < 4; i++) rb[i] = *(const float4*)(Bbase + i * 4);
    }
    {
        float* As = sm;            float* Bs = sm + ABUF;
#pragma unroll
        for (int i = 0; i < 4; i++) {
            const int k0 = kcA + i * 4;
            As[(k0 + 0) * KSTR + rowA] = f2tf(ra[i].x);
            As[(k0 + 1) * KSTR + rowA] = f2tf(ra[i].y);
            As[(k0 + 2) * KSTR + rowA] = f2tf(ra[i].z);
            As[(k0 + 3) * KSTR + rowA] = f2tf(ra[i].w);
        }
        if (TRANS) {
#pragma unroll
            for (int i = 0; i < 4; i++) {
                float4 o = make_float4(f2tf(rb[i].x), f2tf(rb[i].y),
                                       f2tf(rb[i].z), f2tf(rb[i].w));
                *(float4*)&Bs[kB * KSTR + nB + i * 4] = o;
            }
        } else {
#pragma unroll
            for (int i = 0; i < 4; i++) {
                const int k0 = kcB + i * 4;
                Bs[(k0 + 0) * KSTR + nB2] = f2tf(rb[i].x);
                Bs[(k0 + 1) * KSTR + nB2] = f2tf(rb[i].y);
                Bs[(k0 + 2) * KSTR + nB2] = f2tf(rb[i].z);
                Bs[(k0 + 3) * KSTR + nB2] = f2tf(rb[i].w);
            }
        }
    }
    __syncthreads();

    for (int kt = 0; kt < NT; kt++) {
        // ---- prefetch next tile (gmem -> regs) ----
        if (kt + 1 < NT) {
            const float* ap = Abase + (kt + 1) * 32;
#pragma unroll
            for (int i = 0; i < 4; i++) ra[i] = *(const float4*)(ap + i * 4);
            if (TRANS) {
                const float* bp = Bbase + (size_t)(kt + 1) * 32 * ldb;
#pragma unroll
                for (int i = 0; i < 4; i++) rb[i] = *(const float4*)(bp + i * 4);
            } else {
                const float* bp = Bbase + (kt + 1) * 32;
#pragma unroll
                for (int i = 0; i < 4; i++) rb[i] = *(const float4*)(bp + i * 4);
            }
        }

        // ---- mma over current stage ----
        const float* As = sm + (kt & 1) * 2 * ABUF;
        const float* Bs = As + ABUF;
#pragma unroll
        for (int kk = 0; kk < 4; kk++) {
            const int kr = kk * 8 + tig;
            const float* pa = &As[kr * KSTR + wm + g];
            const float* pb = &Bs[kr * KSTR + wn + g];
            float af[4][4], bf[4][2];
#pragma unroll
            for (int mt = 0; mt < 4; mt++) {
                af[mt][0] = pa[mt * 16];
                af[mt][1] = pa[mt * 16 + 8];
                af[mt][2] = pa[4 * KSTR + mt * 16];
                af[mt][3] = pa[4 * KSTR + mt * 16 + 8];
            }
#pragma unroll
            for (int nt = 0; nt < 4; nt++) {
                bf[nt][0] = pb[nt * 8];
                bf[nt][1] = pb[4 * KSTR + nt * 8];
            }
#pragma unroll
            for (int mt = 0; mt < 4; mt++)
#pragma unroll
                for (int nt = 0; nt < 4; nt++)
                    mma1688(acc[mt][nt], af[mt][0], af[mt][1], af[mt][2], af[mt][3],
                            bf[nt][0], bf[nt][1]);
        }

        // ---- store prefetched tile (regs -> other stage) ----
        if (kt + 1 < NT) {
            float* An = sm + ((kt + 1) & 1) * 2 * ABUF;
            float* Bn = An + ABUF;
#pragma unroll
            for (int i = 0; i < 4; i++) {
                const int k0 = kcA + i * 4;
                An[(k0 + 0) * KSTR + rowA] = f2tf(ra[i].x);
                An[(k0 + 1) * KSTR + rowA] = f2tf(ra[i].y);
                An[(k0 + 2) * KSTR + rowA] = f2tf(ra[i].z);
                An[(k0 + 3) * KSTR + rowA] = f2tf(ra[i].w);
            }
            if (TRANS) {
#pragma unroll
                for (int i = 0; i < 4; i++) {
                    float4 o = make_float4(f2tf(rb[i].x), f2tf(rb[i].y),
                                           f2tf(rb[i].z), f2tf(rb[i].w));
                    *(float4*)&Bn[kB * KSTR + nB + i * 4] = o;
                }
            } else {
#pragma unroll
                for (int i = 0; i < 4; i++) {
                    const int k0 = kcB + i * 4;
                    Bn[(k0 + 0) * KSTR + nB2] = f2tf(rb[i].x);
                    Bn[(k0 + 1) * KSTR + nB2] = f2tf(rb[i].y);
                    Bn[(k0 + 2) * KSTR + nB2] = f2tf(rb[i].z);
                    Bn[(k0 + 3) * KSTR + nB2] = f2tf(rb[i].w);
                }
            }
            __syncthreads();
        }
    }

    // ---- epilogue ----
#pragma unroll
    for (int mt = 0; mt < 4; mt++) {
        const int r0 = by * 128 + wm + mt * 16 + g;
#pragma unroll
        for (int nt = 0; nt < 4; nt++) {
            const int col = bx * 128 + wn + nt * 8 + 2 * tig;
            float c0 = acc[mt][nt][0], c1 = acc[mt][nt][1];
            float c2 = acc[mt][nt][2], c3 = acc[mt][nt][3];
            if (EPI == 1) {
                c0 *= scale; c1 *= scale; c2 *= scale; c3 *= scale;
            } else if (EPI >= 2) {
                const float b0 = bias[col], b1 = bias[col + 1];
                c0 += b0; c1 += b1; c2 += b0; c3 += b1;
                if (EPI == 3) {
                    c0 = 0.5f * c0 * (1.0f + erff(c0 * 0.7071067811865476f));
                    c1 = 0.5f * c1 * (1.0f + erff(c1 * 0.7071067811865476f));
                    c2 = 0.5f * c2 * (1.0f + erff(c2 * 0.7071067811865476f));
                    c3 = 0.5f * c3 * (1.0f + erff(c3 * 0.7071067811865476f));
                }
            }
            *(float2*)(C + (size_t)r0 * ldc + col) = make_float2(c0, c1);
            *(float2*)(C + (size_t)(r0 + 8) * ldc + col) = make_float2(c2, c3);
        }
    }
}

// ---------------- embedding + sinusoidal positional encoding ---------------
__global__ void embed_k(const int* __restrict__ x, const float* __restrict__ emb,
                        float* __restrict__ xe)
{
    const int row = blockIdx.x;
    const int t = row & (TSEQ - 1);
    const int tok = x[row];
    const float* e = emb + (size_t)tok * KDIM;
    for (int c = threadIdx.x; c < KDIM; c += blockDim.x) {
        const int j = c >> 1;
        const float expo = (2.0f * (float)(2 * j)) / (float)KDIM;
        const float div = powf(10000.0f, expo);
        const float ang = (float)t / div;
        const float pe = (c & 1) ? cosf(ang) : sinf(ang);
        xe[(size_t)row * KDIM + c] = e[c] + pe;
    }
}

// ---------------- row softmax over T=1024 -----------------------------------
__global__ void __launch_bounds__(256) softmax_k(float* __restrict__ s)
{
    float* p = s + (size_t)blockIdx.x * TSEQ;
    const int tid = threadIdx.x;
    __shared__ float sh[8];

    float v[4];
    float m = -3.4e38f;
#pragma unroll
    for (int i = 0; i < 4; i++) { v[i] = p[tid + i * 256]; m = fmaxf(m, v[i]); }
#pragma unroll
    for (int o = 16; o > 0; o >>= 1) m = fmaxf(m, __shfl_xor_sync(0xffffffffu, m, o));
    if ((tid & 31) == 0) sh[tid >> 5] = m;
    __syncthreads();
    m = fmaxf(fmaxf(fmaxf(sh[0], sh[1]), fmaxf(sh[2], sh[3])),
              fmaxf(fmaxf(sh[4], sh[5]), fmaxf(sh[6], sh[7])));
    __syncthreads();

    float sum = 0.f;
#pragma unroll
    for (int i = 0; i < 4; i++) { v[i] = expf(v[i] - m); sum += v[i]; }
#pragma unroll
    for (int o = 16; o > 0; o >>= 1) sum += __shfl_xor_sync(0xffffffffu, sum, o);
    if ((tid & 31) == 0) sh[tid >> 5] = sum;
    __syncthreads();
    sum = sh[0] + sh[1] + sh[2] + sh[3] + sh[4] + sh[5] + sh[6] + sh[7];
    const float inv = 1.0f / sum;
#pragma unroll
    for (int i = 0; i < 4; i++) p[tid + i * 256] = v[i] * inv;
}

// ---------------- layernorm over K=768 --------------------------------------
__global__ void __launch_bounds__(256) ln_k(const float* __restrict__ in,
                                            float* __restrict__ out,
                                            const float* __restrict__ gw,
                                            const float* __restrict__ bw)
{
    const float* p = in + (size_t)blockIdx.x * KDIM;
    float* o = out + (size_t)blockIdx.x * KDIM;
    const int tid = threadIdx.x;
    __shared__ float sh[8];

    float v[3];
    float s = 0.f;
#pragma unroll
    for (int i = 0; i < 3; i++) { v[i] = p[tid + i * 256]; s += v[i]; }
#pragma unroll
    for (int off = 16; off > 0; off >>= 1) s += __shfl_xor_sync(0xffffffffu, s, off);
    if ((tid & 31) == 0) sh[tid >> 5] = s;
    __syncthreads();
    const float mu = (sh[0] + sh[1] + sh[2] + sh[3] + sh[4] + sh[5] + sh[6] + sh[7])
                     * (1.0f / (float)KDIM);
    __syncthreads();

    float vs = 0.f;
#pragma unroll
    for (int i = 0; i < 3; i++) { const float d = v[i] - mu; vs += d * d; }
#pragma unroll
    for (int off = 16; off > 0; off >>= 1) vs += __shfl_xor_sync(0xffffffffu, vs, off);
    if ((tid & 31) == 0) sh[tid >> 5] = vs;
    __syncthreads();
    const float var = (sh[0] + sh[1] + sh[2] + sh[3] + sh[4] + sh[5] + sh[6] + sh[7])
                      * (1.0f / (float)KDIM);
    const float inv = rsqrtf(var + 1e-5f);
#pragma unroll
    for (int i = 0; i < 3; i++) {
        const int c = tid + i * 256;
        o[c] = (v[i] - mu) * inv * gw[c] + bw[c];
    }
}

// ---------------- host dispatch ----------------------------------------------
template <int EPI, bool TR>
static inline void launch_gemm(const float* A, const float* B, float* C, const float* bias,
                               int M, int N, int Kd, int lda, int ldb, int ldc,
                               long long zAb, long long zAh, long long zBb, long long zBh,
                               long long zCb, long long zCh, int Z, int Hn, float scale)
{
    static bool configured = false;
    cudaFuncSetAttribute(gemm_mma<EPI, TR>,
                         cudaFuncAttributeMaxDynamicSharedMemorySize, SMEM_MMA);
    (void)configured;
    dim3 g(N / 128, M / 128, Z);
    gemm_mma<EPI, TR><<<g, 256, SMEM_MMA>>>(A, B, C, bias, Kd, lda, ldb, ldc,
                                            zAb, zAh, zBb, zBh, zCb, zCh, Hn, scale);
}

extern "C" void kernel_launch(void* const* d_in, const int* in_sizes, int n_in,
                              void* d_out, int out_size)
{
    const int*   x    = (const int*)  d_in[0];
    const float* emb  = (const float*)d_in[1];
    const float* Wq   = (const float*)d_in[2];
    const float* Wk   = (const float*)d_in[3];
    const float* Wv   = (const float*)d_in[4];
    const float* Wu   = (const float*)d_in[5];
    const float* bu   = (const float*)d_in[6];
    const float* ln1g = (const float*)d_in[7];
    const float* ln1b = (const float*)d_in[8];
    const float* Wf1  = (const float*)d_in[9];
    const float* bf1  = (const float*)d_in[10];
    const float* Wf2  = (const float*)d_in[11];
    const float* bf2  = (const float*)d_in[12];
    const float* ln2g = (const float*)d_in[13];
    const float* ln2b = (const float*)d_in[14];
    const float* lnfg = (const float*)d_in[15];
    const float* lnfb = (const float*)d_in[16];
    const float* Wout = (const float*)d_in[17];
    const float* bout = (const float*)d_in[18];
    float* out = (float*)d_out;

    float *xe, *q, *k, *v, *sc, *y, *t1, *t2, *ff;
    cudaGetSymbolAddress((void**)&xe, g_xe);
    cudaGetSymbolAddress((void**)&q,  g_q);
    cudaGetSymbolAddress((void**)&k,  g_k);
    cudaGetSymbolAddress((void**)&v,  g_v);
    cudaGetSymbolAddress((void**)&sc, g_s);
    cudaGetSymbolAddress((void**)&y,  g_y);
    cudaGetSymbolAddress((void**)&t1, g_t1);
    cudaGetSymbolAddress((void**)&t2, g_t2);
    cudaGetSymbolAddress((void**)&ff, g_ff);

    const float scale = 1.0f / sqrtf((float)KDIM);

    embed_k<<<BT, 256>>>(x, emb, xe);

    for (int l = 0; l < 2; l++) {
        const float* wq = Wq + (size_t)l * KDIM * KH;
        const float* wk = Wk + (size_t)l * KDIM * KH;
        const float* wv = Wv + (size_t)l * KDIM * KH;
        const float* wu = Wu + (size_t)l * KH * KDIM;

        // QKV: [2048,768] x [768,6144]  (weights [K,N] -> TRANS)
        launch_gemm<0, true>(xe, wq, q, nullptr, BT, KH, KDIM, KDIM, KH, KH,
                             0, 0, 0, 0, 0, 0, 1, 1, 0.f);
        launch_gemm<0, true>(xe, wk, k, nullptr, BT, KH, KDIM, KDIM, KH, KH,
                             0, 0, 0, 0, 0, 0, 1, 1, 0.f);
        launch_gemm<0, true>(xe, wv, v, nullptr, BT, KH, KDIM, KDIM, KH, KH,
                             0, 0, 0, 0, 0, 0, 1, 1, 0.f);

        // scores[b,h] = Q_h K_h^T * scale  (B gmem [N=s, K=d] -> no trans)
        launch_gemm<1, false>(q, k, sc, nullptr, TSEQ, TSEQ, KDIM, KH, KH, TSEQ,
                              (long long)TSEQ * KH, KDIM,
                              (long long)TSEQ * KH, KDIM,
                              (long long)HEADS * TSEQ * TSEQ, (long long)TSEQ * TSEQ,
                              NBATCH * HEADS, HEADS, scale);

        softmax_k<<<NBATCH * HEADS * TSEQ, 256>>>(sc);

        // y[b,:,h,:] = P_h @ V_h   (V gmem [K=s, N=d] -> TRANS)
        launch_gemm<0, true>(sc, v, y, nullptr, TSEQ, KDIM, TSEQ, TSEQ, KH, KH,
                             (long long)HEADS * TSEQ * TSEQ, (long long)TSEQ * TSEQ,
                             (long long)TSEQ * KH, KDIM,
                             (long long)TSEQ * KH, KDIM,
                             NBATCH * HEADS, HEADS, 0.f);

        // att = y @ Wu + bu
        launch_gemm<2, true>(y, wu, t1, bu + l * KDIM, BT, KDIM, KH, KH, KDIM, KDIM,
                             0, 0, 0, 0, 0, 0, 1, 1, 0.f);
        ln_k<<<BT, 256>>>(t1, t2, ln1g + l * KDIM, ln1b + l * KDIM);

        // FFN
        launch_gemm<3, true>(t2, Wf1 + (size_t)l * KDIM * FFD, ff, bf1 + l * FFD,
                             BT, FFD, KDIM, KDIM, FFD, FFD, 0, 0, 0, 0, 0, 0, 1, 1, 0.f);
        launch_gemm<2, true>(ff, Wf2 + (size_t)l * FFD * KDIM, t1, bf2 + l * KDIM,
                             BT, KDIM, FFD, FFD, KDIM, KDIM, 0, 0, 0, 0, 0, 0, 1, 1, 0.f);
        ln_k<<<BT, 256>>>(t1, xe, ln2g + l * KDIM, ln2b + l * KDIM);
    }

    ln_k<<<BT, 256>>>(xe, t2, lnfg, lnfb);

    // logits = xf @ Wout + bout : [2048,768] x [768,32000]
    launch_gemm<2, true>(t2, Wout, out, bout, BT, VOCAB, KDIM, KDIM, VOCAB, VOCAB,
                         0, 0, 0, 0, 0, 0, 1, 1, 0.f);
}

// round 4
// speedup vs baseline: 1.5885x; 1.2525x over previous
#include <cuda_runtime.h>
#include <math.h>
#include <stdint.h>

#define KDIM   768
#define HEADS  8
#define KH     6144
#define TSEQ   1024
#define NBATCH 2
#define BT     2048
#define VOCAB  32000
#define FFD    3072

// ---------------- scratch (device globals; no runtime allocation) ----------
__device__ float g_xe[BT * KDIM];
__device__ float g_q [BT * KH];
__device__ float g_k [BT * KH];
__device__ float g_v [BT * KH];
__device__ float g_s [(size_t)NBATCH * HEADS * TSEQ * TSEQ];  // 64 MB
__device__ float g_y [BT * KH];
__device__ float g_t1[BT * KDIM];
__device__ float g_t2[BT * KDIM];
__device__ float g_ff[BT * FFD];

// ---------------- helpers ----------------------------------------------------
__device__ __forceinline__ float f2tf(float f) {
    uint32_t r; asm("cvt.rna.tf32.f32 %0, %1;" : "=r"(r) : "f"(f));
    return __uint_as_float(r);
}
__device__ __forceinline__ void mma1688(float c[4],
                                        float a0, float a1, float a2, float a3,
                                        float b0, float b1) {
    asm volatile(
        "mma.sync.aligned.m16n8k8.row.col.f32.tf32.tf32.f32 "
        "{%0,%1,%2,%3}, {%4,%5,%6,%7}, {%8,%9}, {%0,%1,%2,%3};"
        : "+f"(c[0]), "+f"(c[1]), "+f"(c[2]), "+f"(c[3])
        : "r"(__float_as_uint(a0)), "r"(__float_as_uint(a1)),
          "r"(__float_as_uint(a2)), "r"(__float_as_uint(a3)),
          "r"(__float_as_uint(b0)), "r"(__float_as_uint(b1)));
}

// ---------------- tf32 tensor GEMM, fragment-ordered smem --------------------
// Block tile 128x128, BK=32, 256 threads (8 warps: 2 M x 4 N), warp tile 64x32.
// Smem per stage: AFRAG[8 m16][4 k8][32 lane][4 slot]  = 4096 floats (16KB)
//                 BFRAG[16 n8][4 k8][32 lane][2 slot]  = 4096 floats (16KB)
// Fragment load = 1x ld.shared.v4 (A) / 1x ld.shared.v2 (B) per mma block.
//   TRANS=false: gmem B is [N,K] row-major (QK^T)
//   TRANS=true : gmem B is [K,N] row-major (weights, V)
// EPI: 0 none, 1 *scale, 2 +bias, 3 +bias + exact GELU
#define AST 4096
#define BST 4096
#define STG (AST + BST)
#define SMEM_MMA (2 * STG * 4)   // 65536 bytes

template <int EPI, bool TRANS>
__global__ void __launch_bounds__(256) gemm_mma(
    const float* __restrict__ A, const float* __restrict__ B,
    float* __restrict__ C, const float* __restrict__ bias,
    int Kd, int lda, int ldb, int ldc,
    long long zAb, long long zAh, long long zBb, long long zBh,
    long long zCb, long long zCh, int Hn, float scale)
{
    extern __shared__ float sm[];   // [A0|B0|A1|B1]

    const int tid = threadIdx.x;
    const int lane = tid & 31, wid = tid >> 5;
    const int g = lane >> 2, tig = lane & 3;
    const int wm = (wid & 1) * 64, wn = (wid >> 1) * 32;
    const int mbase = (wid & 1) * 4, nbase = (wid >> 1) * 4;
    const int bx = blockIdx.x, by = blockIdx.y, bz = blockIdx.z;
    {
        const int zb = bz / Hn, zh = bz % Hn;
        A += (size_t)zb * zAb + (size_t)zh * zAh;
        B += (size_t)zb * zBb + (size_t)zh * zBh;
        C += (size_t)zb * zCb + (size_t)zh * zCh;
    }

    // ---- staging lane geometry ----
    const int rowA = tid >> 1, kcA = (tid & 1) * 16;       // A gmem: [M,K]
    const int mbA = rowA >> 4, gA = rowA & 7, hiA = (rowA >> 3) & 1;
    const float* Abase = A + (size_t)(by * 128 + rowA) * lda + kcA;

    // B TRANS=true : [K,N]; thread covers k=tid>>3 (one row), n = (tid&7)*16..+15
    const int kB = tid >> 3, nB = (tid & 7) * 16;
    const int ksB = kB >> 3, tigB = kB & 3, slotB = (kB >> 2) & 1;
    // B TRANS=false: [N,K]; thread covers n=tid>>1, k = (tid&1)*16..+15
    const int nB2 = tid >> 1, kcB = (tid & 1) * 16;
    const int nbB = nB2 >> 3, gB = nB2 & 7;
    const float* Bbase = TRANS ? (B + (size_t)kB * ldb + bx * 128 + nB)
                               : (B + (size_t)(bx * 128 + nB2) * ldb + kcB);

    float acc[4][4][4];
#pragma unroll
    for (int i = 0; i < 4; i++)
#pragma unroll
        for (int j = 0; j < 4; j++)
#pragma unroll
            for (int c = 0; c < 4; c++) acc[i][j][c] = 0.f;

    const int NT = Kd >> 5;
    float4 ra[4], rb[4];

    // ---- stage tile 0 ----
#pragma unroll
    for (int i = 0; i < 4; i++) ra[i] = *(const float4*)(Abase + i * 4);
#pragma unroll
    for (int i = 0; i < 4; i++)
        rb[i] = TRANS ? *(const float4*)(Bbase + i * 4)
                      : *(const float4*)(Bbase + i * 4);
    {
        float* As = sm; float* Bs = sm + AST;
#pragma unroll
        for (int i = 0; i < 4; i++) {
            const int k0 = kcA + i * 4;
            const int ks = k0 >> 3, slot = hiA + ((k0 >> 2) & 1) * 2;
            float* p = As + ((mbA * 4 + ks) * 32 + gA * 4) * 4 + slot;
            p[0] = f2tf(ra[i].x); p[4] = f2tf(ra[i].y);
            p[8] = f2tf(ra[i].z); p[12] = f2tf(ra[i].w);
        }
        if (TRANS) {
#pragma unroll
            for (int i = 0; i < 4; i++) {
                const int n0 = nB + i * 4, g0 = n0 & 7, nb = n0 >> 3;
                float* p = Bs + ((nb * 4 + ksB) * 32 + g0 * 4 + tigB) * 2 + slotB;
                p[0] = f2tf(rb[i].x); p[8] = f2tf(rb[i].y);
                p[16] = f2tf(rb[i].z); p[24] = f2tf(rb[i].w);
            }
        } else {
#pragma unroll
            for (int i = 0; i < 4; i++) {
                const int k0 = kcB + i * 4;
                const int ks = k0 >> 3, slot = (k0 >> 2) & 1;
                float* p = Bs + ((nbB * 4 + ks) * 32 + gB * 4) * 2 + slot;
                p[0] = f2tf(rb[i].x); p[2] = f2tf(rb[i].y);
                p[4] = f2tf(rb[i].z); p[6] = f2tf(rb[i].w);
            }
        }
    }
    __syncthreads();

    for (int kt = 0; kt < NT; kt++) {
        // ---- prefetch next tile to regs ----
        if (kt + 1 < NT) {
            const float* ap = Abase + (kt + 1) * 32;
#pragma unroll
            for (int i = 0; i < 4; i++) ra[i] = *(const float4*)(ap + i * 4);
            if (TRANS) {
                const float* bp = Bbase + (size_t)(kt + 1) * 32 * ldb;
#pragma unroll
                for (int i = 0; i < 4; i++) rb[i] = *(const float4*)(bp + i * 4);
            } else {
                const float* bp = Bbase + (kt + 1) * 32;
#pragma unroll
                for (int i = 0; i < 4; i++) rb[i] = *(const float4*)(bp + i * 4);
            }
        }

        // ---- mma over current stage ----
        const float* As = sm + (kt & 1) * STG;
        const float* Bs = As + AST;
#pragma unroll
        for (int ks = 0; ks < 4; ks++) {
            float4 af[4]; float2 bf[4];
#pragma unroll
            for (int mt = 0; mt < 4; mt++)
                af[mt] = *(const float4*)(As + (((mbase + mt) * 4 + ks) * 32 + lane) * 4);
#pragma unroll
            for (int nt = 0; nt < 4; nt++)
                bf[nt] = *(const float2*)(Bs + (((nbase + nt) * 4 + ks) * 32 + lane) * 2);
#pragma unroll
            for (int mt = 0; mt < 4; mt++)
#pragma unroll
                for (int nt = 0; nt < 4; nt++)
                    mma1688(acc[mt][nt], af[mt].x, af[mt].y, af[mt].z, af[mt].w,
                            bf[nt].x, bf[nt].y);
        }

        // ---- store prefetched tile into other stage ----
        if (kt + 1 < NT) {
            float* An = sm + ((kt + 1) & 1) * STG;
            float* Bn = An + AST;
#pragma unroll
            for (int i = 0; i < 4; i++) {
                const int k0 = kcA + i * 4;
                const int ks = k0 >> 3, slot = hiA + ((k0 >> 2) & 1) * 2;
                float* p = An + ((mbA * 4 + ks) * 32 + gA * 4) * 4 + slot;
                p[0] = f2tf(ra[i].x); p[4] = f2tf(ra[i].y);
                p[8] = f2tf(ra[i].z); p[12] = f2tf(ra[i].w);
            }
            if (TRANS) {
#pragma unroll
                for (int i = 0; i < 4; i++) {
                    const int n0 = nB + i * 4, g0 = n0 & 7, nb = n0 >> 3;
                    float* p = Bn + ((nb * 4 + ksB) * 32 + g0 * 4 + tigB) * 2 + slotB;
                    p[0] = f2tf(rb[i].x); p[8] = f2tf(rb[i].y);
                    p[16] = f2tf(rb[i].z); p[24] = f2tf(rb[i].w);
                }
            } else {
#pragma unroll
                for (int i = 0; i < 4; i++) {
                    const int k0 = kcB + i * 4;
                    const int ks = k0 >> 3, slot = (k0 >> 2) & 1;
                    float* p = Bn + ((nbB * 4 + ks) * 32 + gB * 4) * 2 + slot;
                    p[0] = f2tf(rb[i].x); p[2] = f2tf(rb[i].y);
                    p[4] = f2tf(rb[i].z); p[6] = f2tf(rb[i].w);
                }
            }
            __syncthreads();
        }
    }

    // ---- epilogue ----
#pragma unroll
    for (int mt = 0; mt < 4; mt++) {
        const int r0 = by * 128 + wm + mt * 16 + g;
#pragma unroll
        for (int nt = 0; nt < 4; nt++) {
            const int col = bx * 128 + wn + nt * 8 + 2 * tig;
            float c0 = acc[mt][nt][0], c1 = acc[mt][nt][1];
            float c2 = acc[mt][nt][2], c3 = acc[mt][nt][3];
            if (EPI == 1) {
                c0 *= scale; c1 *= scale; c2 *= scale; c3 *= scale;
            } else if (EPI >= 2) {
                const float b0 = bias[col], b1 = bias[col + 1];
                c0 += b0; c1 += b1; c2 += b0; c3 += b1;
                if (EPI == 3) {
                    c0 = 0.5f * c0 * (1.0f + erff(c0 * 0.7071067811865476f));
                    c1 = 0.5f * c1 * (1.0f + erff(c1 * 0.7071067811865476f));
                    c2 = 0.5f * c2 * (1.0f + erff(c2 * 0.7071067811865476f));
                    c3 = 0.5f * c3 * (1.0f + erff(c3 * 0.7071067811865476f));
                }
            }
            *(float2*)(C + (size_t)r0 * ldc + col) = make_float2(c0, c1);
            *(float2*)(C + (size_t)(r0 + 8) * ldc + col) = make_float2(c2, c3);
        }
    }
}

// ---------------- embedding + sinusoidal positional encoding ---------------
__global__ void embed_k(const int* __restrict__ x, const float* __restrict__ emb,
                        float* __restrict__ xe)
{
    const int row = blockIdx.x;
    const int t = row & (TSEQ - 1);
    const int tok = x[row];
    const float* e = emb + (size_t)tok * KDIM;
    for (int c = threadIdx.x; c < KDIM; c += blockDim.x) {
        const int j = c >> 1;
        const float expo = (2.0f * (float)(2 * j)) / (float)KDIM;
        const float div = powf(10000.0f, expo);
        const float ang = (float)t / div;
        const float pe = (c & 1) ? cosf(ang) : sinf(ang);
        xe[(size_t)row * KDIM + c] = e[c] + pe;
    }
}

// ---------------- row softmax over T=1024 -----------------------------------
__global__ void __launch_bounds__(256) softmax_k(float* __restrict__ s)
{
    float* p = s + (size_t)blockIdx.x * TSEQ;
    const int tid = threadIdx.x;
    __shared__ float sh[8];

    float v[4];
    float m = -3.4e38f;
#pragma unroll
    for (int i = 0; i < 4; i++) { v[i] = p[tid + i * 256]; m = fmaxf(m, v[i]); }
#pragma unroll
    for (int o = 16; o > 0; o >>= 1) m = fmaxf(m, __shfl_xor_sync(0xffffffffu, m, o));
    if ((tid & 31) == 0) sh[tid >> 5] = m;
    __syncthreads();
    m = fmaxf(fmaxf(fmaxf(sh[0], sh[1]), fmaxf(sh[2], sh[3])),
              fmaxf(fmaxf(sh[4], sh[5]), fmaxf(sh[6], sh[7])));
    __syncthreads();

    float sum = 0.f;
#pragma unroll
    for (int i = 0; i < 4; i++) { v[i] = expf(v[i] - m); sum += v[i]; }
#pragma unroll
    for (int o = 16; o > 0; o >>= 1) sum += __shfl_xor_sync(0xffffffffu, sum, o);
    if ((tid & 31) == 0) sh[tid >> 5] = sum;
    __syncthreads();
    sum = sh[0] + sh[1] + sh[2] + sh[3] + sh[4] + sh[5] + sh[6] + sh[7];
    const float inv = 1.0f / sum;
#pragma unroll
    for (int i = 0; i < 4; i++) p[tid + i * 256] = v[i] * inv;
}

// ---------------- layernorm over K=768 --------------------------------------
__global__ void __launch_bounds__(256) ln_k(const float* __restrict__ in,
                                            float* __restrict__ out,
                                            const float* __restrict__ gw,
                                            const float* __restrict__ bw)
{
    const float* p = in + (size_t)blockIdx.x * KDIM;
    float* o = out + (size_t)blockIdx.x * KDIM;
    const int tid = threadIdx.x;
    __shared__ float sh[8];

    float v[3];
    float s = 0.f;
#pragma unroll
    for (int i = 0; i < 3; i++) { v[i] = p[tid + i * 256]; s += v[i]; }
#pragma unroll
    for (int off = 16; off > 0; off >>= 1) s += __shfl_xor_sync(0xffffffffu, s, off);
    if ((tid & 31) == 0) sh[tid >> 5] = s;
    __syncthreads();
    const float mu = (sh[0] + sh[1] + sh[2] + sh[3] + sh[4] + sh[5] + sh[6] + sh[7])
                     * (1.0f / (float)KDIM);
    __syncthreads();

    float vs = 0.f;
#pragma unroll
    for (int i = 0; i < 3; i++) { const float d = v[i] - mu; vs += d * d; }
#pragma unroll
    for (int off = 16; off > 0; off >>= 1) vs += __shfl_xor_sync(0xffffffffu, vs, off);
    if ((tid & 31) == 0) sh[tid >> 5] = vs;
    __syncthreads();
    const float var = (sh[0] + sh[1] + sh[2] + sh[3] + sh[4] + sh[5] + sh[6] + sh[7])
                      * (1.0f / (float)KDIM);
    const float inv = rsqrtf(var + 1e-5f);
#pragma unroll
    for (int i = 0; i < 3; i++) {
        const int c = tid + i * 256;
        o[c] = (v[i] - mu) * inv * gw[c] + bw[c];
    }
}

// ---------------- host dispatch ----------------------------------------------
template <int EPI, bool TR>
static inline void launch_gemm(const float* A, const float* B, float* C, const float* bias,
                               int M, int N, int Kd, int lda, int ldb, int ldc,
                               long long zAb, long long zAh, long long zBb, long long zBh,
                               long long zCb, long long zCh, int Z, int Hn, float scale)
{
    cudaFuncSetAttribute(gemm_mma<EPI, TR>,
                         cudaFuncAttributeMaxDynamicSharedMemorySize, SMEM_MMA);
    dim3 g(N / 128, M / 128, Z);
    gemm_mma<EPI, TR><<<g, 256, SMEM_MMA>>>(A, B, C, bias, Kd, lda, ldb, ldc,
                                            zAb, zAh, zBb, zBh, zCb, zCh, Hn, scale);
}

extern "C" void kernel_launch(void* const* d_in, const int* in_sizes, int n_in,
                              void* d_out, int out_size)
{
    const int*   x    = (const int*)  d_in[0];
    const float* emb  = (const float*)d_in[1];
    const float* Wq   = (const float*)d_in[2];
    const float* Wk   = (const float*)d_in[3];
    const float* Wv   = (const float*)d_in[4];
    const float* Wu   = (const float*)d_in[5];
    const float* bu   = (const float*)d_in[6];
    const float* ln1g = (const float*)d_in[7];
    const float* ln1b = (const float*)d_in[8];
    const float* Wf1  = (const float*)d_in[9];
    const float* bf1  = (const float*)d_in[10];
    const float* Wf2  = (const float*)d_in[11];
    const float* bf2  = (const float*)d_in[12];
    const float* ln2g = (const float*)d_in[13];
    const float* ln2b = (const float*)d_in[14];
    const float* lnfg = (const float*)d_in[15];
    const float* lnfb = (const float*)d_in[16];
    const float* Wout = (const float*)d_in[17];
    const float* bout = (const float*)d_in[18];
    float* out = (float*)d_out;

    float *xe, *q, *k, *v, *sc, *y, *t1, *t2, *ff;
    cudaGetSymbolAddress((void**)&xe, g_xe);
    cudaGetSymbolAddress((void**)&q,  g_q);
    cudaGetSymbolAddress((void**)&k,  g_k);
    cudaGetSymbolAddress((void**)&v,  g_v);
    cudaGetSymbolAddress((void**)&sc, g_s);
    cudaGetSymbolAddress((void**)&y,  g_y);
    cudaGetSymbolAddress((void**)&t1, g_t1);
    cudaGetSymbolAddress((void**)&t2, g_t2);
    cudaGetSymbolAddress((void**)&ff, g_ff);

    const float scale = 1.0f / sqrtf((float)KDIM);

    embed_k<<<BT, 256>>>(x, emb, xe);

    for (int l = 0; l < 2; l++) {
        const float* wq = Wq + (size_t)l * KDIM * KH;
        const float* wk = Wk + (size_t)l * KDIM * KH;
        const float* wv = Wv + (size_t)l * KDIM * KH;
        const float* wu = Wu + (size_t)l * KH * KDIM;

        // QKV: [2048,768] x [768,6144]  (weights [K,N] -> TRANS)
        launch_gemm<0, true>(xe, wq, q, nullptr, BT, KH, KDIM, KDIM, KH, KH,
                             0, 0, 0, 0, 0, 0, 1, 1, 0.f);
        launch_gemm<0, true>(xe, wk, k, nullptr, BT, KH, KDIM, KDIM, KH, KH,
                             0, 0, 0, 0, 0, 0, 1, 1, 0.f);
        launch_gemm<0, true>(xe, wv, v, nullptr, BT, KH, KDIM, KDIM, KH, KH,
                             0, 0, 0, 0, 0, 0, 1, 1, 0.f);

        // scores[b,h] = Q_h K_h^T * scale  (B gmem [N=s, K=d] -> no trans)
        launch_gemm<1, false>(q, k, sc, nullptr, TSEQ, TSEQ, KDIM, KH, KH, TSEQ,
                              (long long)TSEQ * KH, KDIM,
                              (long long)TSEQ * KH, KDIM,
                              (long long)HEADS * TSEQ * TSEQ, (long long)TSEQ * TSEQ,
                              NBATCH * HEADS, HEADS, scale);

        softmax_k<<<NBATCH * HEADS * TSEQ, 256>>>(sc);

        // y[b,:,h,:] = P_h @ V_h   (V gmem [K=s, N=d] -> TRANS)
        launch_gemm<0, true>(sc, v, y, nullptr, TSEQ, KDIM, TSEQ, TSEQ, KH, KH,
                             (long long)HEADS * TSEQ * TSEQ, (long long)TSEQ * TSEQ,
                             (long long)TSEQ * KH, KDIM,
                             (long long)TSEQ * KH, KDIM,
                             NBATCH * HEADS, HEADS, 0.f);

        // att = y @ Wu + bu
        launch_gemm<2, true>(y, wu, t1, bu + l * KDIM, BT, KDIM, KH, KH, KDIM, KDIM,
                             0, 0, 0, 0, 0, 0, 1, 1, 0.f);
        ln_k<<<BT, 256>>>(t1, t2, ln1g + l * KDIM, ln1b + l * KDIM);

        // FFN
        launch_gemm<3, true>(t2, Wf1 + (size_t)l * KDIM * FFD, ff, bf1 + l * FFD,
                             BT, FFD, KDIM, KDIM, FFD, FFD, 0, 0, 0, 0, 0, 0, 1, 1, 0.f);
        launch_gemm<2, true>(ff, Wf2 + (size_t)l * FFD * KDIM, t1, bf2 + l * KDIM,
                             BT, KDIM, FFD, FFD, KDIM, KDIM, 0, 0, 0, 0, 0, 0, 1, 1, 0.f);
        ln_k<<<BT, 256>>>(t1, xe, ln2g + l * KDIM, ln2b + l * KDIM);
    }

    ln_k<<<BT, 256>>>(xe, t2, lnfg, lnfb);

    // logits = xf @ Wout + bout : [2048,768] x [768,32000]
    launch_gemm<2, true>(t2, Wout, out, bout, BT, VOCAB, KDIM, KDIM, VOCAB, VOCAB,
                         0, 0, 0, 0, 0, 0, 1, 1, 0.f);
}

// round 5
// speedup vs baseline: 1.6828x; 1.0594x over previous
#include <cuda_runtime.h>
#include <math.h>
#include <stdint.h>

#define KDIM   768
#define HEADS  8
#define KH     6144
#define TSEQ   1024
#define NBATCH 2
#define BT     2048
#define VOCAB  32000
#define FFD    3072

// ---------------- scratch (device globals; no runtime allocation) ----------
__device__ float g_xe[BT * KDIM];
__device__ float g_q [BT * KH];
__device__ float g_k [BT * KH];
__device__ float g_v [BT * KH];
__device__ float g_s [(size_t)NBATCH * HEADS * TSEQ * TSEQ];  // 64 MB
__device__ float g_y [BT * KH];
__device__ float g_t1[BT * KDIM];
__device__ float g_t2[BT * KDIM];
__device__ float g_ff[BT * FFD];

// ---------------- helpers ----------------------------------------------------
__device__ __forceinline__ float f2tf(float f) {
    uint32_t r; asm("cvt.rna.tf32.f32 %0, %1;" : "=r"(r) : "f"(f));
    return __uint_as_float(r);
}
__device__ __forceinline__ void mma1688(float c[4],
                                        float a0, float a1, float a2, float a3,
                                        float b0, float b1) {
    asm volatile(
        "mma.sync.aligned.m16n8k8.row.col.f32.tf32.tf32.f32 "
        "{%0,%1,%2,%3}, {%4,%5,%6,%7}, {%8,%9}, {%0,%1,%2,%3};"
        : "+f"(c[0]), "+f"(c[1]), "+f"(c[2]), "+f"(c[3])
        : "r"(__float_as_uint(a0)), "r"(__float_as_uint(a1)),
          "r"(__float_as_uint(a2)), "r"(__float_as_uint(a3)),
          "r"(__float_as_uint(b0)), "r"(__float_as_uint(b1)));
}

// ---------------- tf32 tensor GEMM ------------------------------------------
// Block tile 128 x BN (BN=256 or 128), BK=16, 256 threads (8 warps, 2M x 4N),
// warp tile 64 x (BN/4). Double-buffered smem, conflict-free layouts:
//   A: [mb8][ks2][slot4][lane32]          (2048 floats) — f4 writes, scalar reads
//   B: [nb(BN/8): stride 136][ks: 68][s: 32][tig: 8][g: 1]  — padded strides
//      rotate banks; f4 (TRANS) / scalar (non-TRANS) writes, scalar reads.
//   TRANS=false: gmem B is [N,K] row-major (QK^T), BN must be 256
//   TRANS=true : gmem B is [K,N] row-major (weights, V)
// EPI: 0 none, 1 *scale, 2 +bias, 3 +bias + exact GELU
#define BK   16
#define AOFF 0
#define BOFF 2048

template <int EPI, bool TRANS, int BN>
__global__ void __launch_bounds__(256) gemm_mma(
    const float* __restrict__ A, const float* __restrict__ B,
    float* __restrict__ C, const float* __restrict__ bias,
    int Kd, int lda, int ldb, int ldc,
    long long zAb, long long zAh, long long zBb, long long zBh,
    long long zCb, long long zCh, int Hn, float scale)
{
    constexpr int NT_ = BN / 32;            // nt count per warp (8 or 4)
    constexpr int BST = (BN / 8) * 136;     // B stage floats
    constexpr int STAGE = 2048 + BST;
    extern __shared__ float sm[];           // [stage0 | stage1]

    const int tid = threadIdx.x;
    const int lane = tid & 31, wid = tid >> 5;
    const int g = lane >> 2, tig = lane & 3;
    const int wm = (wid & 1) * 64, wn = (wid >> 1) * (BN / 4);
    const int mbase = (wid & 1) * 4, nbase = (wid >> 1) * (BN / 32);
    const int bx = blockIdx.x, by = blockIdx.y, bz = blockIdx.z;
    {
        const int zb = bz / Hn, zh = bz % Hn;
        A += (size_t)zb * zAb + (size_t)zh * zAh;
        B += (size_t)zb * zBb + (size_t)zh * zBh;
        C += (size_t)zb * zCb + (size_t)zh * zCh;
    }

    // ---- A staging geometry: 128 rows x 16 k, 8 floats/thread ----
    const int rowA = tid >> 1, kcbit = tid & 1;
    const int mbA = rowA >> 4, gA = rowA & 7, hiA = (rowA >> 3) & 1;
    const float* Abase = A + (size_t)(by * 128 + rowA) * lda + kcbit * 8;

    // ---- B staging geometry ----
    // TRANS: gmem [K,N]: kRow = tid&15, nC = (tid>>4)*(BN/16)
    const int kRowT = tid & 15;
    const int tigT = kRowT & 3, sT = (kRowT >> 2) & 1, ksT = kRowT >> 3;
    const int nCT = (tid >> 4) * (BN / 16);
    const float* BbT = B + (size_t)kRowT * ldb + bx * BN + nCT;
    // non-TRANS (BN==256 only): gmem [N,K]: one row per thread
    const int nbN = tid >> 3, gN = tid & 7;
    const float* BbN = B + (size_t)(bx * BN + tid) * ldb;

    float acc[4][NT_][4];
#pragma unroll
    for (int i = 0; i < 4; i++)
#pragma unroll
        for (int j = 0; j < NT_; j++)
#pragma unroll
            for (int c = 0; c < 4; c++) acc[i][j][c] = 0.f;

    const int NTILES = Kd / BK;

    // ---- staging closure ----
    auto stage = [&](int kt, float* dst) {
        // A: two float4 loads -> two float4 stores
        float4 a0 = *(const float4*)(Abase + kt * BK);
        float4 a1 = *(const float4*)(Abase + kt * BK + 4);
        float* pa = dst + AOFF + mbA * 256 + kcbit * 128 + hiA * 32 + gA * 4;
        *(float4*)pa = make_float4(f2tf(a0.x), f2tf(a0.y), f2tf(a0.z), f2tf(a0.w));
        *(float4*)(pa + 64) = make_float4(f2tf(a1.x), f2tf(a1.y), f2tf(a1.z), f2tf(a1.w));
        // B
        if (TRANS) {
            const float* bp = BbT + (size_t)kt * BK * ldb;
#pragma unroll
            for (int f = 0; f < BN / 64; f++) {
                float4 v = *(const float4*)(bp + f * 4);
                const int n0 = nCT + f * 4;
                const int nb = n0 >> 3, g0 = n0 & 7;
                float* pb = dst + BOFF + nb * 136 + ksT * 68 + sT * 32 + tigT * 8 + g0;
                *(float4*)pb = make_float4(f2tf(v.x), f2tf(v.y), f2tf(v.z), f2tf(v.w));
            }
        } else {
            const float* bp = BbN + kt * BK;
#pragma unroll
            for (int f = 0; f < 4; f++) {
                float4 v = *(const float4*)(bp + f * 4);
                float* pb = dst + BOFF + nbN * 136 + (f >> 1) * 68 + (f & 1) * 32 + gN;
                pb[0]  = f2tf(v.x);
                pb[8]  = f2tf(v.y);
                pb[16] = f2tf(v.z);
                pb[24] = f2tf(v.w);
            }
        }
    };

    stage(0, sm);
    __syncthreads();

    for (int kt = 0; kt < NTILES; kt++) {
        const float* As = sm + (kt & 1) * STAGE;

        // mma over current stage
#pragma unroll
        for (int ks = 0; ks < 2; ks++) {
            float af[4][4];
#pragma unroll
            for (int mt = 0; mt < 4; mt++) {
                const float* pa = As + AOFF + (mbase + mt) * 256 + ks * 128 + lane;
                af[mt][0] = pa[0]; af[mt][1] = pa[32];
                af[mt][2] = pa[64]; af[mt][3] = pa[96];
            }
#pragma unroll
            for (int nt = 0; nt < NT_; nt++) {
                const float* pb = As + BOFF + (nbase + nt) * 136 + ks * 68 + tig * 8 + g;
                const float b0 = pb[0], b1 = pb[32];
#pragma unroll
                for (int mt = 0; mt < 4; mt++)
                    mma1688(acc[mt][nt], af[mt][0], af[mt][1], af[mt][2], af[mt][3],
                            b0, b1);
            }
        }

        // stage next tile into the other buffer
        if (kt + 1 < NTILES) {
            stage(kt + 1, sm + ((kt + 1) & 1) * STAGE);
        }
        __syncthreads();
    }

    // ---- epilogue ----
#pragma unroll
    for (int mt = 0; mt < 4; mt++) {
        const int r0 = by * 128 + wm + mt * 16 + g;
#pragma unroll
        for (int nt = 0; nt < NT_; nt++) {
            const int col = bx * BN + wn + nt * 8 + 2 * tig;
            float c0 = acc[mt][nt][0], c1 = acc[mt][nt][1];
            float c2 = acc[mt][nt][2], c3 = acc[mt][nt][3];
            if (EPI == 1) {
                c0 *= scale; c1 *= scale; c2 *= scale; c3 *= scale;
            } else if (EPI >= 2) {
                const float b0 = bias[col], b1 = bias[col + 1];
                c0 += b0; c1 += b1; c2 += b0; c3 += b1;
                if (EPI == 3) {
                    c0 = 0.5f * c0 * (1.0f + erff(c0 * 0.7071067811865476f));
                    c1 = 0.5f * c1 * (1.0f + erff(c1 * 0.7071067811865476f));
                    c2 = 0.5f * c2 * (1.0f + erff(c2 * 0.7071067811865476f));
                    c3 = 0.5f * c3 * (1.0f + erff(c3 * 0.7071067811865476f));
                }
            }
            *(float2*)(C + (size_t)r0 * ldc + col) = make_float2(c0, c1);
            *(float2*)(C + (size_t)(r0 + 8) * ldc + col) = make_float2(c2, c3);
        }
    }
}

// ---------------- embedding + sinusoidal positional encoding ---------------
__global__ void embed_k(const int* __restrict__ x, const float* __restrict__ emb,
                        float* __restrict__ xe)
{
    const int row = blockIdx.x;
    const int t = row & (TSEQ - 1);
    const int tok = x[row];
    const float* e = emb + (size_t)tok * KDIM;
    for (int c = threadIdx.x; c < KDIM; c += blockDim.x) {
        const int j = c >> 1;
        const float expo = (2.0f * (float)(2 * j)) / (float)KDIM;
        const float div = powf(10000.0f, expo);
        const float ang = (float)t / div;
        const float pe = (c & 1) ? cosf(ang) : sinf(ang);
        xe[(size_t)row * KDIM + c] = e[c] + pe;
    }
}

// ---------------- row softmax over T=1024 -----------------------------------
__global__ void __launch_bounds__(256) softmax_k(float* __restrict__ s)
{
    float* p = s + (size_t)blockIdx.x * TSEQ;
    const int tid = threadIdx.x;
    __shared__ float sh[8];

    float v[4];
    float m = -3.4e38f;
#pragma unroll
    for (int i = 0; i < 4; i++) { v[i] = p[tid + i * 256]; m = fmaxf(m, v[i]); }
#pragma unroll
    for (int o = 16; o > 0; o >>= 1) m = fmaxf(m, __shfl_xor_sync(0xffffffffu, m, o));
    if ((tid & 31) == 0) sh[tid >> 5] = m;
    __syncthreads();
    m = fmaxf(fmaxf(fmaxf(sh[0], sh[1]), fmaxf(sh[2], sh[3])),
              fmaxf(fmaxf(sh[4], sh[5]), fmaxf(sh[6], sh[7])));
    __syncthreads();

    float sum = 0.f;
#pragma unroll
    for (int i = 0; i < 4; i++) { v[i] = expf(v[i] - m); sum += v[i]; }
#pragma unroll
    for (int o = 16; o > 0; o >>= 1) sum += __shfl_xor_sync(0xffffffffu, sum, o);
    if ((tid & 31) == 0) sh[tid >> 5] = sum;
    __syncthreads();
    sum = sh[0] + sh[1] + sh[2] + sh[3] + sh[4] + sh[5] + sh[6] + sh[7];
    const float inv = 1.0f / sum;
#pragma unroll
    for (int i = 0; i < 4; i++) p[tid + i * 256] = v[i] * inv;
}

// ---------------- layernorm over K=768 --------------------------------------
__global__ void __launch_bounds__(256) ln_k(const float* __restrict__ in,
                                            float* __restrict__ out,
                                            const float* __restrict__ gw,
                                            const float* __restrict__ bw)
{
    const float* p = in + (size_t)blockIdx.x * KDIM;
    float* o = out + (size_t)blockIdx.x * KDIM;
    const int tid = threadIdx.x;
    __shared__ float sh[8];

    float v[3];
    float s = 0.f;
#pragma unroll
    for (int i = 0; i < 3; i++) { v[i] = p[tid + i * 256]; s += v[i]; }
#pragma unroll
    for (int off = 16; off > 0; off >>= 1) s += __shfl_xor_sync(0xffffffffu, s, off);
    if ((tid & 31) == 0) sh[tid >> 5] = s;
    __syncthreads();
    const float mu = (sh[0] + sh[1] + sh[2] + sh[3] + sh[4] + sh[5] + sh[6] + sh[7])
                     * (1.0f / (float)KDIM);
    __syncthreads();

    float vs = 0.f;
#pragma unroll
    for (int i = 0; i < 3; i++) { const float d = v[i] - mu; vs += d * d; }
#pragma unroll
    for (int off = 16; off > 0; off >>= 1) vs += __shfl_xor_sync(0xffffffffu, vs, off);
    if ((tid & 31) == 0) sh[tid >> 5] = vs;
    __syncthreads();
    const float var = (sh[0] + sh[1] + sh[2] + sh[3] + sh[4] + sh[5] + sh[6] + sh[7])
                      * (1.0f / (float)KDIM);
    const float inv = rsqrtf(var + 1e-5f);
#pragma unroll
    for (int i = 0; i < 3; i++) {
        const int c = tid + i * 256;
        o[c] = (v[i] - mu) * inv * gw[c] + bw[c];
    }
}

// ---------------- host dispatch ----------------------------------------------
template <int EPI, bool TR, int BN>
static inline void launch_gemm(const float* A, const float* B, float* C, const float* bias,
                               int M, int N, int Kd, int lda, int ldb, int ldc,
                               long long zAb, long long zAh, long long zBb, long long zBh,
                               long long zCb, long long zCh, int Z, int Hn, float scale)
{
    constexpr int STAGE = 2048 + (BN / 8) * 136;
    constexpr int SMEMB = 2 * STAGE * 4;
    cudaFuncSetAttribute(gemm_mma<EPI, TR, BN>,
                         cudaFuncAttributeMaxDynamicSharedMemorySize, SMEMB);
    dim3 g(N / BN, M / 128, Z);
    gemm_mma<EPI, TR, BN><<<g, 256, SMEMB>>>(A, B, C, bias, Kd, lda, ldb, ldc,
                                             zAb, zAh, zBb, zBh, zCb, zCh, Hn, scale);
}

extern "C" void kernel_launch(void* const* d_in, const int* in_sizes, int n_in,
                              void* d_out, int out_size)
{
    const int*   x    = (const int*)  d_in[0];
    const float* emb  = (const float*)d_in[1];
    const float* Wq   = (const float*)d_in[2];
    const float* Wk   = (const float*)d_in[3];
    const float* Wv   = (const float*)d_in[4];
    const float* Wu   = (const float*)d_in[5];
    const float* bu   = (const float*)d_in[6];
    const float* ln1g = (const float*)d_in[7];
    const float* ln1b = (const float*)d_in[8];
    const float* Wf1  = (const float*)d_in[9];
    const float* bf1  = (const float*)d_in[10];
    const float* Wf2  = (const float*)d_in[11];
    const float* bf2  = (const float*)d_in[12];
    const float* ln2g = (const float*)d_in[13];
    const float* ln2b = (const float*)d_in[14];
    const float* lnfg = (const float*)d_in[15];
    const float* lnfb = (const float*)d_in[16];
    const float* Wout = (const float*)d_in[17];
    const float* bout = (const float*)d_in[18];
    float* out = (float*)d_out;

    float *xe, *q, *k, *v, *sc, *y, *t1, *t2, *ff;
    cudaGetSymbolAddress((void**)&xe, g_xe);
    cudaGetSymbolAddress((void**)&q,  g_q);
    cudaGetSymbolAddress((void**)&k,  g_k);
    cudaGetSymbolAddress((void**)&v,  g_v);
    cudaGetSymbolAddress((void**)&sc, g_s);
    cudaGetSymbolAddress((void**)&y,  g_y);
    cudaGetSymbolAddress((void**)&t1, g_t1);
    cudaGetSymbolAddress((void**)&t2, g_t2);
    cudaGetSymbolAddress((void**)&ff, g_ff);

    const float scale = 1.0f / sqrtf((float)KDIM);

    embed_k<<<BT, 256>>>(x, emb, xe);

    for (int l = 0; l < 2; l++) {
        const float* wq = Wq + (size_t)l * KDIM * KH;
        const float* wk = Wk + (size_t)l * KDIM * KH;
        const float* wv = Wv + (size_t)l * KDIM * KH;
        const float* wu = Wu + (size_t)l * KH * KDIM;

        // QKV: [2048,768] x [768,6144]
        launch_gemm<0, true, 256>(xe, wq, q, nullptr, BT, KH, KDIM, KDIM, KH, KH,
                                  0, 0, 0, 0, 0, 0, 1, 1, 0.f);
        launch_gemm<0, true, 256>(xe, wk, k, nullptr, BT, KH, KDIM, KDIM, KH, KH,
                                  0, 0, 0, 0, 0, 0, 1, 1, 0.f);
        launch_gemm<0, true, 256>(xe, wv, v, nullptr, BT, KH, KDIM, KDIM, KH, KH,
                                  0, 0, 0, 0, 0, 0, 1, 1, 0.f);

        // scores[b,h] = Q_h K_h^T * scale  (B gmem [N=s, K=d])
        launch_gemm<1, false, 256>(q, k, sc, nullptr, TSEQ, TSEQ, KDIM, KH, KH, TSEQ,
                                   (long long)TSEQ * KH, KDIM,
                                   (long long)TSEQ * KH, KDIM,
                                   (long long)HEADS * TSEQ * TSEQ, (long long)TSEQ * TSEQ,
                                   NBATCH * HEADS, HEADS, scale);

        softmax_k<<<NBATCH * HEADS * TSEQ, 256>>>(sc);

        // y[b,:,h,:] = P_h @ V_h   (V gmem [K=s, N=d], N=768 -> BN128)
        launch_gemm<0, true, 128>(sc, v, y, nullptr, TSEQ, KDIM, TSEQ, TSEQ, KH, KH,
                                  (long long)HEADS * TSEQ * TSEQ, (long long)TSEQ * TSEQ,
                                  (long long)TSEQ * KH, KDIM,
                                  (long long)TSEQ * KH, KDIM,
                                  NBATCH * HEADS, HEADS, 0.f);

        // att = y @ Wu + bu  (N=768 -> BN128)
        launch_gemm<2, true, 128>(y, wu, t1, bu + l * KDIM, BT, KDIM, KH, KH, KDIM, KDIM,
                                  0, 0, 0, 0, 0, 0, 1, 1, 0.f);
        ln_k<<<BT, 256>>>(t1, t2, ln1g + l * KDIM, ln1b + l * KDIM);

        // FFN
        launch_gemm<3, true, 256>(t2, Wf1 + (size_t)l * KDIM * FFD, ff, bf1 + l * FFD,
                                  BT, FFD, KDIM, KDIM, FFD, FFD, 0, 0, 0, 0, 0, 0, 1, 1, 0.f);
        launch_gemm<2, true, 128>(ff, Wf2 + (size_t)l * FFD * KDIM, t1, bf2 + l * KDIM,
                                  BT, KDIM, FFD, FFD, KDIM, KDIM, 0, 0, 0, 0, 0, 0, 1, 1, 0.f);
        ln_k<<<BT, 256>>>(t1, xe, ln2g + l * KDIM, ln2b + l * KDIM);
    }

    ln_k<<<BT, 256>>>(xe, t2, lnfg, lnfb);

    // logits = xf @ Wout + bout : [2048,768] x [768,32000]
    launch_gemm<2, true, 256>(t2, Wout, out, bout, BT, VOCAB, KDIM, KDIM, VOCAB, VOCAB,
                              0, 0, 0, 0, 0, 0, 1, 1, 0.f);
}

// round 6
// speedup vs baseline: 1.7004x; 1.0104x over previous
#include <cuda_runtime.h>
#include <math.h>
#include <stdint.h>

#define KDIM   768
#define HEADS  8
#define KH     6144
#define TSEQ   1024
#define NBATCH 2
#define BT     2048
#define VOCAB  32000
#define FFD    3072

// ---------------- scratch (device globals; no runtime allocation) ----------
__device__ float g_xe[BT * KDIM];
__device__ float g_q [BT * KH];
__device__ float g_k [BT * KH];
__device__ float g_v [BT * KH];
__device__ float g_s [(size_t)NBATCH * HEADS * TSEQ * TSEQ];  // 64 MB
__device__ float g_y [BT * KH];
__device__ float g_t1[BT * KDIM];
__device__ float g_t2[BT * KDIM];
__device__ float g_ff[BT * FFD];

// ---------------- helpers ----------------------------------------------------
__device__ __forceinline__ float f2tf(float f) {
    uint32_t r; asm("cvt.rna.tf32.f32 %0, %1;" : "=r"(r) : "f"(f));
    return __uint_as_float(r);
}
__device__ __forceinline__ void mma1688(float c[4],
                                        float a0, float a1, float a2, float a3,
                                        float b0, float b1) {
    asm volatile(
        "mma.sync.aligned.m16n8k8.row.col.f32.tf32.tf32.f32 "
        "{%0,%1,%2,%3}, {%4,%5,%6,%7}, {%8,%9}, {%0,%1,%2,%3};"
        : "+f"(c[0]), "+f"(c[1]), "+f"(c[2]), "+f"(c[3])
        : "r"(__float_as_uint(a0)), "r"(__float_as_uint(a1)),
          "r"(__float_as_uint(a2)), "r"(__float_as_uint(a3)),
          "r"(__float_as_uint(b0)), "r"(__float_as_uint(b1)));
}

// ---------------- tf32 tensor GEMM ------------------------------------------
// Block tile 64 x BN, BK=16, 256 threads (8 warps: 2M x 4N), warp 32 x BN/4.
// 2 CTAs/SM (launch_bounds). Double-buffered smem, bank-exact layouts:
//  A: mb*288 + ks*144 + q*72 + hi*32 + lane   (1152 fl)
//     writes: one STS.128/thread, conflict-free per 8-lane phase
//     reads : 4 scalar LDS per fragment, conflict-free
//  B TRANS ([K,N] gmem): nb*NBs + ks*72 + lane*2 + s   (v2 reads)
//     NBs = 168 (BN=256) / 176 (BN=128); scalar writes bijective on 32 banks
//  B non-TRANS ([N,K] gmem, BN=256 only): nb*136 + ks*68 + s*32 + tig*8 + g
//     scalar reads + conflict-free scalar writes
// EPI: 0 none, 1 *scale, 2 +bias, 3 +bias + exact GELU
#define ASZ 1152

template <int EPI, bool TRANS, int BN>
__global__ void __launch_bounds__(256, 2) gemm_mma(
    const float* __restrict__ A, const float* __restrict__ B,
    float* __restrict__ C, const float* __restrict__ bias,
    int Kd, int lda, int ldb, int ldc,
    long long zAb, long long zAh, long long zBb, long long zBh,
    long long zCb, long long zCh, int Hn, float scale)
{
    constexpr int NT_ = BN / 32;                       // n8 frags per warp
    constexpr int NBs = (BN == 256) ? 168 : 176;       // TRANS nb stride
    constexpr int BSZ = TRANS ? (BN / 8) * NBs : (BN / 8) * 136;
    constexpr int STAGE = ASZ + BSZ;
    constexpr int NF = BN / 64;                        // f4 per thread (B TRANS)
    extern __shared__ float sm[];

    const int tid = threadIdx.x;
    const int lane = tid & 31, wid = tid >> 5;
    const int g = lane >> 2, tig = lane & 3;
    const int mb0 = (wid & 1) * 2, nb0 = (wid >> 1) * NT_;
    const int bx = blockIdx.x, by = blockIdx.y, bz = blockIdx.z;
    {
        const int zb = bz / Hn, zh = bz % Hn;
        A += (size_t)zb * zAb + (size_t)zh * zAh;
        B += (size_t)zb * zBb + (size_t)zh * zBh;
        C += (size_t)zb * zCb + (size_t)zh * zCh;
    }

    // ---- A staging: 64 rows x 16 k, one f4 per thread ----
    const int rowA = tid >> 2;
    const int gA = rowA & 7, hiA = (rowA >> 3) & 1, mbA = rowA >> 4;
    const int ksA = (tid & 3) >> 1, qA = tid & 1;
    const int aoff = mbA * 288 + ksA * 144 + qA * 72 + hiA * 32 + gA * 4;
    const float* Abase = A + (size_t)(by * 64 + rowA) * lda + (tid & 3) * 4;

    // ---- B staging geometry ----
    // TRANS: kRow = tid&15, n-chunk (tid>>4)*(BN/16)
    const int kRT = tid & 15;
    const int tigT = kRT & 3, sT = (kRT >> 2) & 1, ksT = kRT >> 3;
    const int n0T = (tid >> 4) * (BN / 16);
    const float* BbT = B + (size_t)kRT * ldb + bx * BN + n0T;
    // non-TRANS: one n-row per thread
    const int nbN = tid >> 3, gN = tid & 7;
    const float* BbN = B + (size_t)(bx * BN + tid) * ldb;

    float acc[2][NT_][4];
#pragma unroll
    for (int i = 0; i < 2; i++)
#pragma unroll
        for (int j = 0; j < NT_; j++)
#pragma unroll
            for (int c = 0; c < 4; c++) acc[i][j][c] = 0.f;

    const int NTILES = Kd >> 4;
    float4 ra, rb[NF > 4 ? NF : 4];

    auto ldg = [&](int kt) {
        ra = *(const float4*)(Abase + kt * 16);
        if (TRANS) {
            const float* bp = BbT + (size_t)kt * 16 * ldb;
#pragma unroll
            for (int j = 0; j < NF; j++) rb[j] = *(const float4*)(bp + j * 4);
        } else {
            const float* bp = BbN + kt * 16;
#pragma unroll
            for (int j = 0; j < 4; j++) rb[j] = *(const float4*)(bp + j * 4);
        }
    };
    auto sts = [&](float* dst) {
        *(float4*)(dst + aoff) =
            make_float4(f2tf(ra.x), f2tf(ra.y), f2tf(ra.z), f2tf(ra.w));
        float* Bst = dst + ASZ;
        if (TRANS) {
#pragma unroll
            for (int j = 0; j < NF; j++) {
                const int nb = (BN == 256) ? (2 * (tid >> 4) + (j >> 1)) : (tid >> 4);
                const int g0 = (4 * j) & 7;
                float* p = Bst + nb * NBs + ksT * 72 + g0 * 8 + tigT * 2 + sT;
                p[0]  = f2tf(rb[j].x);
                p[8]  = f2tf(rb[j].y);
                p[16] = f2tf(rb[j].z);
                p[24] = f2tf(rb[j].w);
            }
        } else {
#pragma unroll
            for (int f = 0; f < 4; f++) {
                float* p = Bst + nbN * 136 + (f >> 1) * 68 + (f & 1) * 32 + gN;
                p[0]  = f2tf(rb[f].x);
                p[8]  = f2tf(rb[f].y);
                p[16] = f2tf(rb[f].z);
                p[24] = f2tf(rb[f].w);
            }
        }
    };

    ldg(0);
    sts(sm);
    __syncthreads();

    for (int kt = 0; kt < NTILES; kt++) {
        const bool more = (kt + 1 < NTILES);
        if (more) ldg(kt + 1);

        const float* As = sm + (kt & 1) * STAGE;
        const float* Bs = As + ASZ;
#pragma unroll
        for (int ks = 0; ks < 2; ks++) {
            float af[2][4];
#pragma unroll
            for (int mt = 0; mt < 2; mt++) {
                const float* pa = As + (mb0 + mt) * 288 + ks * 144 + lane;
                af[mt][0] = pa[0]; af[mt][1] = pa[32];
                af[mt][2] = pa[72]; af[mt][3] = pa[104];
            }
#pragma unroll
            for (int nt = 0; nt < NT_; nt++) {
                float b0, b1;
                if (TRANS) {
                    float2 bv = *(const float2*)(Bs + (nb0 + nt) * NBs + ks * 72 + lane * 2);
                    b0 = bv.x; b1 = bv.y;
                } else {
                    const float* pb = Bs + (nb0 + nt) * 136 + ks * 68 + tig * 8 + g;
                    b0 = pb[0]; b1 = pb[32];
                }
#pragma unroll
                for (int mt = 0; mt < 2; mt++)
                    mma1688(acc[mt][nt], af[mt][0], af[mt][1], af[mt][2], af[mt][3],
                            b0, b1);
            }
        }

        if (more) {
            sts(sm + ((kt + 1) & 1) * STAGE);
            __syncthreads();
        }
    }

    // ---- epilogue ----
#pragma unroll
    for (int mt = 0; mt < 2; mt++) {
        const int r0 = by * 64 + (wid & 1) * 32 + mt * 16 + g;
#pragma unroll
        for (int nt = 0; nt < NT_; nt++) {
            const int col = bx * BN + (wid >> 1) * (BN / 4) + nt * 8 + 2 * tig;
            float c0 = acc[mt][nt][0], c1 = acc[mt][nt][1];
            float c2 = acc[mt][nt][2], c3 = acc[mt][nt][3];
            if (EPI == 1) {
                c0 *= scale; c1 *= scale; c2 *= scale; c3 *= scale;
            } else if (EPI >= 2) {
                const float b0 = bias[col], b1 = bias[col + 1];
                c0 += b0; c1 += b1; c2 += b0; c3 += b1;
                if (EPI == 3) {
                    c0 = 0.5f * c0 * (1.0f + erff(c0 * 0.7071067811865476f));
                    c1 = 0.5f * c1 * (1.0f + erff(c1 * 0.7071067811865476f));
                    c2 = 0.5f * c2 * (1.0f + erff(c2 * 0.7071067811865476f));
                    c3 = 0.5f * c3 * (1.0f + erff(c3 * 0.7071067811865476f));
                }
            }
            *(float2*)(C + (size_t)r0 * ldc + col) = make_float2(c0, c1);
            *(float2*)(C + (size_t)(r0 + 8) * ldc + col) = make_float2(c2, c3);
        }
    }
}

// ---------------- embedding + sinusoidal positional encoding ---------------
__global__ void embed_k(const int* __restrict__ x, const float* __restrict__ emb,
                        float* __restrict__ xe)
{
    const int row = blockIdx.x;
    const int t = row & (TSEQ - 1);
    const int tok = x[row];
    const float* e = emb + (size_t)tok * KDIM;
    for (int c = threadIdx.x; c < KDIM; c += blockDim.x) {
        const int j = c >> 1;
        const float expo = (2.0f * (float)(2 * j)) / (float)KDIM;
        const float div = powf(10000.0f, expo);
        const float ang = (float)t / div;
        const float pe = (c & 1) ? cosf(ang) : sinf(ang);
        xe[(size_t)row * KDIM + c] = e[c] + pe;
    }
}

// ---------------- row softmax over T=1024 -----------------------------------
__global__ void __launch_bounds__(256) softmax_k(float* __restrict__ s)
{
    float* p = s + (size_t)blockIdx.x * TSEQ;
    const int tid = threadIdx.x;
    __shared__ float sh[8];

    float v[4];
    float m = -3.4e38f;
#pragma unroll
    for (int i = 0; i < 4; i++) { v[i] = p[tid + i * 256]; m = fmaxf(m, v[i]); }
#pragma unroll
    for (int o = 16; o > 0; o >>= 1) m = fmaxf(m, __shfl_xor_sync(0xffffffffu, m, o));
    if ((tid & 31) == 0) sh[tid >> 5] = m;
    __syncthreads();
    m = fmaxf(fmaxf(fmaxf(sh[0], sh[1]), fmaxf(sh[2], sh[3])),
              fmaxf(fmaxf(sh[4], sh[5]), fmaxf(sh[6], sh[7])));
    __syncthreads();

    float sum = 0.f;
#pragma unroll
    for (int i = 0; i < 4; i++) { v[i] = expf(v[i] - m); sum += v[i]; }
#pragma unroll
    for (int o = 16; o > 0; o >>= 1) sum += __shfl_xor_sync(0xffffffffu, sum, o);
    if ((tid & 31) == 0) sh[tid >> 5] = sum;
    __syncthreads();
    sum = sh[0] + sh[1] + sh[2] + sh[3] + sh[4] + sh[5] + sh[6] + sh[7];
    const float inv = 1.0f / sum;
#pragma unroll
    for (int i = 0; i < 4; i++) p[tid + i * 256] = v[i] * inv;
}

// ---------------- layernorm over K=768 --------------------------------------
__global__ void __launch_bounds__(256) ln_k(const float* __restrict__ in,
                                            float* __restrict__ out,
                                            const float* __restrict__ gw,
                                            const float* __restrict__ bw)
{
    const float* p = in + (size_t)blockIdx.x * KDIM;
    float* o = out + (size_t)blockIdx.x * KDIM;
    const int tid = threadIdx.x;
    __shared__ float sh[8];

    float v[3];
    float s = 0.f;
#pragma unroll
    for (int i = 0; i < 3; i++) { v[i] = p[tid + i * 256]; s += v[i]; }
#pragma unroll
    for (int off = 16; off > 0; off >>= 1) s += __shfl_xor_sync(0xffffffffu, s, off);
    if ((tid & 31) == 0) sh[tid >> 5] = s;
    __syncthreads();
    const float mu = (sh[0] + sh[1] + sh[2] + sh[3] + sh[4] + sh[5] + sh[6] + sh[7])
                     * (1.0f / (float)KDIM);
    __syncthreads();

    float vs = 0.f;
#pragma unroll
    for (int i = 0; i < 3; i++) { const float d = v[i] - mu; vs += d * d; }
#pragma unroll
    for (int off = 16; off > 0; off >>= 1) vs += __shfl_xor_sync(0xffffffffu, vs, off);
    if ((tid & 31) == 0) sh[tid >> 5] = vs;
    __syncthreads();
    const float var = (sh[0] + sh[1] + sh[2] + sh[3] + sh[4] + sh[5] + sh[6] + sh[7])
                      * (1.0f / (float)KDIM);
    const float inv = rsqrtf(var + 1e-5f);
#pragma unroll
    for (int i = 0; i < 3; i++) {
        const int c = tid + i * 256;
        o[c] = (v[i] - mu) * inv * gw[c] + bw[c];
    }
}

// ---------------- host dispatch ----------------------------------------------
template <int EPI, bool TR, int BN>
static inline void launch_gemm(const float* A, const float* B, float* C, const float* bias,
                               int M, int N, int Kd, int lda, int ldb, int ldc,
                               long long zAb, long long zAh, long long zBb, long long zBh,
                               long long zCb, long long zCh, int Z, int Hn, float scale)
{
    constexpr int NBs = (BN == 256) ? 168 : 176;
    constexpr int BSZ = TR ? (BN / 8) * NBs : (BN / 8) * 136;
    constexpr int SMEMB = 2 * (ASZ + BSZ) * 4;
    cudaFuncSetAttribute(gemm_mma<EPI, TR, BN>,
                         cudaFuncAttributeMaxDynamicSharedMemorySize, SMEMB);
    dim3 g(N / BN, M / 64, Z);
    gemm_mma<EPI, TR, BN><<<g, 256, SMEMB>>>(A, B, C, bias, Kd, lda, ldb, ldc,
                                             zAb, zAh, zBb, zBh, zCb, zCh, Hn, scale);
}

extern "C" void kernel_launch(void* const* d_in, const int* in_sizes, int n_in,
                              void* d_out, int out_size)
{
    const int*   x    = (const int*)  d_in[0];
    const float* emb  = (const float*)d_in[1];
    const float* Wq   = (const float*)d_in[2];
    const float* Wk   = (const float*)d_in[3];
    const float* Wv   = (const float*)d_in[4];
    const float* Wu   = (const float*)d_in[5];
    const float* bu   = (const float*)d_in[6];
    const float* ln1g = (const float*)d_in[7];
    const float* ln1b = (const float*)d_in[8];
    const float* Wf1  = (const float*)d_in[9];
    const float* bf1  = (const float*)d_in[10];
    const float* Wf2  = (const float*)d_in[11];
    const float* bf2  = (const float*)d_in[12];
    const float* ln2g = (const float*)d_in[13];
    const float* ln2b = (const float*)d_in[14];
    const float* lnfg = (const float*)d_in[15];
    const float* lnfb = (const float*)d_in[16];
    const float* Wout = (const float*)d_in[17];
    const float* bout = (const float*)d_in[18];
    float* out = (float*)d_out;

    float *xe, *q, *k, *v, *sc, *y, *t1, *t2, *ff;
    cudaGetSymbolAddress((void**)&xe, g_xe);
    cudaGetSymbolAddress((void**)&q,  g_q);
    cudaGetSymbolAddress((void**)&k,  g_k);
    cudaGetSymbolAddress((void**)&v,  g_v);
    cudaGetSymbolAddress((void**)&sc, g_s);
    cudaGetSymbolAddress((void**)&y,  g_y);
    cudaGetSymbolAddress((void**)&t1, g_t1);
    cudaGetSymbolAddress((void**)&t2, g_t2);
    cudaGetSymbolAddress((void**)&ff, g_ff);

    const float scale = 1.0f / sqrtf((float)KDIM);

    embed_k<<<BT, 256>>>(x, emb, xe);

    for (int l = 0; l < 2; l++) {
        const float* wq = Wq + (size_t)l * KDIM * KH;
        const float* wk = Wk + (size_t)l * KDIM * KH;
        const float* wv = Wv + (size_t)l * KDIM * KH;
        const float* wu = Wu + (size_t)l * KH * KDIM;

        // QKV: [2048,768] x [768,6144]
        launch_gemm<0, true, 256>(xe, wq, q, nullptr, BT, KH, KDIM, KDIM, KH, KH,
                                  0, 0, 0, 0, 0, 0, 1, 1, 0.f);
        launch_gemm<0, true, 256>(xe, wk, k, nullptr, BT, KH, KDIM, KDIM, KH, KH,
                                  0, 0, 0, 0, 0, 0, 1, 1, 0.f);
        launch_gemm<0, true, 256>(xe, wv, v, nullptr, BT, KH, KDIM, KDIM, KH, KH,
                                  0, 0, 0, 0, 0, 0, 1, 1, 0.f);

        // scores[b,h] = Q_h K_h^T * scale  (B gmem [N=s, K=d])
        launch_gemm<1, false, 256>(q, k, sc, nullptr, TSEQ, TSEQ, KDIM, KH, KH, TSEQ,
                                   (long long)TSEQ * KH, KDIM,
                                   (long long)TSEQ * KH, KDIM,
                                   (long long)HEADS * TSEQ * TSEQ, (long long)TSEQ * TSEQ,
                                   NBATCH * HEADS, HEADS, scale);

        softmax_k<<<NBATCH * HEADS * TSEQ, 256>>>(sc);

        // y[b,:,h,:] = P_h @ V_h   (V gmem [K=s, N=d])
        launch_gemm<0, true, 128>(sc, v, y, nullptr, TSEQ, KDIM, TSEQ, TSEQ, KH, KH,
                                  (long long)HEADS * TSEQ * TSEQ, (long long)TSEQ * TSEQ,
                                  (long long)TSEQ * KH, KDIM,
                                  (long long)TSEQ * KH, KDIM,
                                  NBATCH * HEADS, HEADS, 0.f);

        // att = y @ Wu + bu
        launch_gemm<2, true, 128>(y, wu, t1, bu + l * KDIM, BT, KDIM, KH, KH, KDIM, KDIM,
                                  0, 0, 0, 0, 0, 0, 1, 1, 0.f);
        ln_k<<<BT, 256>>>(t1, t2, ln1g + l * KDIM, ln1b + l * KDIM);

        // FFN
        launch_gemm<3, true, 256>(t2, Wf1 + (size_t)l * KDIM * FFD, ff, bf1 + l * FFD,
                                  BT, FFD, KDIM, KDIM, FFD, FFD, 0, 0, 0, 0, 0, 0, 1, 1, 0.f);
        launch_gemm<2, true, 128>(ff, Wf2 + (size_t)l * FFD * KDIM, t1, bf2 + l * KDIM,
                                  BT, KDIM, FFD, FFD, KDIM, KDIM, 0, 0, 0, 0, 0, 0, 1, 1, 0.f);
        ln_k<<<BT, 256>>>(t1, xe, ln2g + l * KDIM, ln2b + l * KDIM);
    }

    ln_k<<<BT, 256>>>(xe, t2, lnfg, lnfb);

    // logits = xf @ Wout + bout : [2048,768] x [768,32000]
    launch_gemm<2, true, 256>(t2, Wout, out, bout, BT, VOCAB, KDIM, KDIM, VOCAB, VOCAB,
                              0, 0, 0, 0, 0, 0, 1, 1, 0.f);
}

// round 7
// speedup vs baseline: 3.3791x; 1.9872x over previous
#include <cuda_runtime.h>
#include <math.h>
#include <stdint.h>

#define KDIM   768
#define HEADS  8
#define KH     6144
#define TSEQ   1024
#define NBATCH 2
#define BT     2048
#define VOCAB  32000
#define FFD    3072

// ---------------- scratch (device globals; no runtime allocation) ----------
__device__ float g_xe[BT * KDIM];
__device__ float g_q [BT * KH];
__device__ float g_k [BT * KH];
__device__ float g_v [BT * KH];
__device__ float g_s [(size_t)NBATCH * HEADS * TSEQ * TSEQ];  // 64 MB
__device__ float g_y [BT * KH];
__device__ float g_t1[BT * KDIM];
__device__ float g_t2[BT * KDIM];
__device__ float g_ff[BT * FFD];
// tf32-converted weights
__device__ float g_cwq [2 * KDIM * KH];
__device__ float g_cwk [2 * KDIM * KH];
__device__ float g_cwv [2 * KDIM * KH];
__device__ float g_cwu [2 * KH * KDIM];
__device__ float g_cwf1[2 * KDIM * FFD];
__device__ float g_cwf2[2 * FFD * KDIM];
__device__ float g_cwo [KDIM * VOCAB];

// ---------------- helpers ----------------------------------------------------
__device__ __forceinline__ float f2tf(float f) {
    uint32_t r; asm("cvt.rna.tf32.f32 %0, %1;" : "=r"(r) : "f"(f));
    return __uint_as_float(r);
}
__device__ __forceinline__ uint32_t smem_u32(const void* p) {
    uint32_t a;
    asm("{ .reg .u64 t; cvta.to.shared.u64 t, %1; cvt.u32.u64 %0, t; }" : "=r"(a) : "l"(p));
    return a;
}
__device__ __forceinline__ void cp16(uint32_t saddr, const float* g) {
    asm volatile("cp.async.cg.shared.global [%0], [%1], 16;"
                 :: "r"(saddr), "l"(g) : "memory");
}
__device__ __forceinline__ void cp_commit() {
    asm volatile("cp.async.commit_group;" ::: "memory");
}
__device__ __forceinline__ void cp_wait2() {
    asm volatile("cp.async.wait_group 2;" ::: "memory");
}
__device__ __forceinline__ void mma1688(float c[4],
                                        float a0, float a1, float a2, float a3,
                                        float b0, float b1) {
    asm volatile(
        "mma.sync.aligned.m16n8k8.row.col.f32.tf32.tf32.f32 "
        "{%0,%1,%2,%3}, {%4,%5,%6,%7}, {%8,%9}, {%0,%1,%2,%3};"
        : "+f"(c[0]), "+f"(c[1]), "+f"(c[2]), "+f"(c[3])
        : "r"(__float_as_uint(a0)), "r"(__float_as_uint(a1)),
          "r"(__float_as_uint(a2)), "r"(__float_as_uint(a3)),
          "r"(__float_as_uint(b0)), "r"(__float_as_uint(b1)));
}

// ---------------- tf32 GEMM with cp.async 4-stage pipeline -------------------
// Block 64 x BN, BK=16, 256 thr (8 warps 2Mx4N), warp 32 x BN/4. 2 CTAs/SM.
// All operands must already be tf32-rounded fp32 in gmem.
// Smem (per stage): A 1024 fl, word = m*16+k ^ (((m>>1)&7)<<2)
//                   B BN*16 fl:
//        TRANS ([K,N] gmem): word = k*BN+n ^ ((k&7)<<2)
//        !TRANS ([N,K] gmem): word = n*16+k ^ (((n>>1)&7)<<2)
// EPI: 0 none, 1 *scale, 2 +bias, 3 +bias + exact GELU. RND: round output.
template <int EPI, bool TRANS, int BN, bool RND>
__global__ void __launch_bounds__(256, 2) gemm_ca(
    const float* __restrict__ A, const float* __restrict__ B,
    float* __restrict__ C, const float* __restrict__ bias,
    int Kd, int lda, int ldb, int ldc,
    long long zAb, long long zAh, long long zBb, long long zBh,
    long long zCb, long long zCh, int Hn, float scale)
{
    constexpr int NT_ = BN / 32;
    constexpr int BFL = BN * 16;
    constexpr int STG_ = 1024 + BFL;
    extern __shared__ float sm[];
    const uint32_t sbase = smem_u32(sm);

    const int tid = threadIdx.x;
    const int lane = tid & 31, wid = tid >> 5;
    const int g = lane >> 2, tig = lane & 3;
    const int bx = blockIdx.x, by = blockIdx.y, bz = blockIdx.z;
    {
        const int zb = bz / Hn, zh = bz % Hn;
        A += (size_t)zb * zAb + (size_t)zh * zAh;
        B += (size_t)zb * zBb + (size_t)zh * zBh;
        C += (size_t)zb * zCb + (size_t)zh * zCh;
    }

    // ---- cp.async source pointers and smem word offsets ----
    const int mA = tid >> 2, ccA = tid & 3;
    const float* Ag = A + (size_t)(by * 64 + mA) * lda + ccA * 4;
    const uint32_t awrd = (uint32_t)((mA * 16 + ccA * 4) ^ (((mA >> 1) & 7) << 2));

    // B TRANS: k = tid>>4, chunks c = (tid&15) + j*16, n = c*4
    const int kT = tid >> 4;
    const float* BgT = B + (size_t)kT * ldb + bx * BN;
    // B !TRANS: rows n = (tid>>2) + j*64, cc = tid&3
    const int nN = tid >> 2, ccN = tid & 3;
    const float* BgN = B + (size_t)(bx * BN + nN) * ldb + ccN * 4;

    float acc[2][NT_][4];
#pragma unroll
    for (int i = 0; i < 2; i++)
#pragma unroll
        for (int j = 0; j < NT_; j++)
#pragma unroll
            for (int c = 0; c < 4; c++) acc[i][j][c] = 0.f;

    const int NTILES = Kd >> 4;

    auto issue = [&](int kt) {
        const uint32_t sa = sbase + (uint32_t)(kt & 3) * STG_ * 4;
        cp16(sa + awrd * 4, Ag + kt * 16);
        const uint32_t sb = sa + 1024 * 4;
        if (TRANS) {
            const float* bp = BgT + (size_t)kt * 16 * ldb;
#pragma unroll
            for (int j = 0; j < BN / 64; j++) {
                const int c = (tid & 15) + j * 16;
                const uint32_t w = (uint32_t)((kT * BN + c * 4) ^ ((kT & 7) << 2));
                cp16(sb + w * 4, bp + c * 4);
            }
        } else {
            const float* bp = BgN + kt * 16;
#pragma unroll
            for (int j = 0; j < 4; j++) {
                const int n = nN + j * 64;
                const uint32_t w = (uint32_t)((n * 16 + ccN * 4) ^ (((n >> 1) & 7) << 2));
                cp16(sb + w * 4, bp + (size_t)j * 64 * ldb);
            }
        }
    };

#pragma unroll
    for (int s = 0; s < 3; s++) { issue(s); cp_commit(); }

    for (int kt = 0; kt < NTILES; kt++) {
        cp_wait2();
        __syncthreads();

        const float* As = sm + (kt & 3) * STG_;
        const float* Bs = As + 1024;
#pragma unroll
        for (int ks = 0; ks < 2; ks++) {
            float af[2][4];
#pragma unroll
            for (int mt = 0; mt < 2; mt++) {
                const int m0 = (wid & 1) * 32 + mt * 16 + g;
                const int k0 = ks * 8 + tig;
                const int sw0 = ((m0 >> 1) & 7) << 2;
                const int sw1 = (((m0 + 8) >> 1) & 7) << 2;
                af[mt][0] = As[(m0 * 16 + k0) ^ sw0];
                af[mt][1] = As[((m0 + 8) * 16 + k0) ^ sw1];
                af[mt][2] = As[(m0 * 16 + k0 + 4) ^ sw0];
                af[mt][3] = As[((m0 + 8) * 16 + k0 + 4) ^ sw1];
            }
#pragma unroll
            for (int nt = 0; nt < NT_; nt++) {
                const int n0 = (wid >> 1) * (BN / 4) + nt * 8 + g;
                float b0, b1;
                if (TRANS) {
                    const int k0 = ks * 8 + tig;
                    b0 = Bs[(k0 * BN + n0) ^ ((k0 & 7) << 2)];
                    b1 = Bs[((k0 + 4) * BN + n0) ^ (((k0 + 4) & 7) << 2)];
                } else {
                    const int sw = ((n0 >> 1) & 7) << 2;
                    b0 = Bs[(n0 * 16 + ks * 8 + tig) ^ sw];
                    b1 = Bs[(n0 * 16 + ks * 8 + tig + 4) ^ sw];
                }
#pragma unroll
                for (int mt = 0; mt < 2; mt++)
                    mma1688(acc[mt][nt], af[mt][0], af[mt][1], af[mt][2], af[mt][3],
                            b0, b1);
            }
        }

        if (kt + 3 < NTILES) issue(kt + 3);
        cp_commit();
    }

    // ---- epilogue ----
#pragma unroll
    for (int mt = 0; mt < 2; mt++) {
        const int r0 = by * 64 + (wid & 1) * 32 + mt * 16 + g;
#pragma unroll
        for (int nt = 0; nt < NT_; nt++) {
            const int col = bx * BN + (wid >> 1) * (BN / 4) + nt * 8 + 2 * tig;
            float c0 = acc[mt][nt][0], c1 = acc[mt][nt][1];
            float c2 = acc[mt][nt][2], c3 = acc[mt][nt][3];
            if (EPI == 1) {
                c0 *= scale; c1 *= scale; c2 *= scale; c3 *= scale;
            } else if (EPI >= 2) {
                const float b0 = bias[col], b1 = bias[col + 1];
                c0 += b0; c1 += b1; c2 += b0; c3 += b1;
                if (EPI == 3) {
                    c0 = 0.5f * c0 * (1.0f + erff(c0 * 0.7071067811865476f));
                    c1 = 0.5f * c1 * (1.0f + erff(c1 * 0.7071067811865476f));
                    c2 = 0.5f * c2 * (1.0f + erff(c2 * 0.7071067811865476f));
                    c3 = 0.5f * c3 * (1.0f + erff(c3 * 0.7071067811865476f));
                }
            }
            if (RND) {
                c0 = f2tf(c0); c1 = f2tf(c1); c2 = f2tf(c2); c3 = f2tf(c3);
            }
            *(float2*)(C + (size_t)r0 * ldc + col) = make_float2(c0, c1);
            *(float2*)(C + (size_t)(r0 + 8) * ldc + col) = make_float2(c2, c3);
        }
    }
}

// ---------------- weight -> tf32 conversion ---------------------------------
__global__ void cvt_k(const float* __restrict__ s, float* __restrict__ d, int n4)
{
    int i = blockIdx.x * blockDim.x + threadIdx.x;
    if (i < n4) {
        float4 v = ((const float4*)s)[i];
        ((float4*)d)[i] = make_float4(f2tf(v.x), f2tf(v.y), f2tf(v.z), f2tf(v.w));
    }
}

// ---------------- embedding + positional encoding (tf32 out) ---------------
__global__ void embed_k(const int* __restrict__ x, const float* __restrict__ emb,
                        float* __restrict__ xe)
{
    const int row = blockIdx.x;
    const int t = row & (TSEQ - 1);
    const int tok = x[row];
    const float* e = emb + (size_t)tok * KDIM;
    for (int c = threadIdx.x; c < KDIM; c += blockDim.x) {
        const int j = c >> 1;
        const float expo = (2.0f * (float)(2 * j)) / (float)KDIM;
        const float div = powf(10000.0f, expo);
        const float ang = (float)t / div;
        const float pe = (c & 1) ? cosf(ang) : sinf(ang);
        xe[(size_t)row * KDIM + c] = f2tf(e[c] + pe);
    }
}

// ---------------- row softmax over T=1024 (tf32 out) ------------------------
__global__ void __launch_bounds__(256) softmax_k(float* __restrict__ s)
{
    float* p = s + (size_t)blockIdx.x * TSEQ;
    const int tid = threadIdx.x;
    __shared__ float sh[8];

    float v[4];
    float m = -3.4e38f;
#pragma unroll
    for (int i = 0; i < 4; i++) { v[i] = p[tid + i * 256]; m = fmaxf(m, v[i]); }
#pragma unroll
    for (int o = 16; o > 0; o >>= 1) m = fmaxf(m, __shfl_xor_sync(0xffffffffu, m, o));
    if ((tid & 31) == 0) sh[tid >> 5] = m;
    __syncthreads();
    m = fmaxf(fmaxf(fmaxf(sh[0], sh[1]), fmaxf(sh[2], sh[3])),
              fmaxf(fmaxf(sh[4], sh[5]), fmaxf(sh[6], sh[7])));
    __syncthreads();

    float sum = 0.f;
#pragma unroll
    for (int i = 0; i < 4; i++) { v[i] = expf(v[i] - m); sum += v[i]; }
#pragma unroll
    for (int o = 16; o > 0; o >>= 1) sum += __shfl_xor_sync(0xffffffffu, sum, o);
    if ((tid & 31) == 0) sh[tid >> 5] = sum;
    __syncthreads();
    sum = sh[0] + sh[1] + sh[2] + sh[3] + sh[4] + sh[5] + sh[6] + sh[7];
    const float inv = 1.0f / sum;
#pragma unroll
    for (int i = 0; i < 4; i++) p[tid + i * 256] = f2tf(v[i] * inv);
}

// ---------------- layernorm over K=768 (tf32 out) ----------------------------
__global__ void __launch_bounds__(256) ln_k(const float* __restrict__ in,
                                            float* __restrict__ out,
                                            const float* __restrict__ gw,
                                            const float* __restrict__ bw)
{
    const float* p = in + (size_t)blockIdx.x * KDIM;
    float* o = out + (size_t)blockIdx.x * KDIM;
    const int tid = threadIdx.x;
    __shared__ float sh[8];

    float v[3];
    float s = 0.f;
#pragma unroll
    for (int i = 0; i < 3; i++) { v[i] = p[tid + i * 256]; s += v[i]; }
#pragma unroll
    for (int off = 16; off > 0; off >>= 1) s += __shfl_xor_sync(0xffffffffu, s, off);
    if ((tid & 31) == 0) sh[tid >> 5] = s;
    __syncthreads();
    const float mu = (sh[0] + sh[1] + sh[2] + sh[3] + sh[4] + sh[5] + sh[6] + sh[7])
                     * (1.0f / (float)KDIM);
    __syncthreads();

    float vs = 0.f;
#pragma unroll
    for (int i = 0; i < 3; i++) { const float d = v[i] - mu; vs += d * d; }
#pragma unroll
    for (int off = 16; off > 0; off >>= 1) vs += __shfl_xor_sync(0xffffffffu, vs, off);
    if ((tid & 31) == 0) sh[tid >> 5] = vs;
    __syncthreads();
    const float var = (sh[0] + sh[1] + sh[2] + sh[3] + sh[4] + sh[5] + sh[6] + sh[7])
                      * (1.0f / (float)KDIM);
    const float inv = rsqrtf(var + 1e-5f);
#pragma unroll
    for (int i = 0; i < 3; i++) {
        const int c = tid + i * 256;
        o[c] = f2tf((v[i] - mu) * inv * gw[c] + bw[c]);
    }
}

// ---------------- host dispatch ----------------------------------------------
template <int EPI, bool TR, int BN, bool RND>
static inline void launch_gemm(const float* A, const float* B, float* C, const float* bias,
                               int M, int N, int Kd, int lda, int ldb, int ldc,
                               long long zAb, long long zAh, long long zBb, long long zBh,
                               long long zCb, long long zCh, int Z, int Hn, float scale)
{
    constexpr int SMEMB = 4 * (1024 + BN * 16) * 4;
    cudaFuncSetAttribute(gemm_ca<EPI, TR, BN, RND>,
                         cudaFuncAttributeMaxDynamicSharedMemorySize, SMEMB);
    dim3 gr(N / BN, M / 64, Z);
    gemm_ca<EPI, TR, BN, RND><<<gr, 256, SMEMB>>>(A, B, C, bias, Kd, lda, ldb, ldc,
                                                  zAb, zAh, zBb, zBh, zCb, zCh, Hn, scale);
}

static inline void cvt(const float* s, float* d, size_t n)
{
    int n4 = (int)(n / 4);
    cvt_k<<<(n4 + 255) / 256, 256>>>(s, d, n4);
}

extern "C" void kernel_launch(void* const* d_in, const int* in_sizes, int n_in,
                              void* d_out, int out_size)
{
    const int*   x    = (const int*)  d_in[0];
    const float* emb  = (const float*)d_in[1];
    const float* Wq   = (const float*)d_in[2];
    const float* Wk   = (const float*)d_in[3];
    const float* Wv   = (const float*)d_in[4];
    const float* Wu   = (const float*)d_in[5];
    const float* bu   = (const float*)d_in[6];
    const float* ln1g = (const float*)d_in[7];
    const float* ln1b = (const float*)d_in[8];
    const float* Wf1  = (const float*)d_in[9];
    const float* bf1  = (const float*)d_in[10];
    const float* Wf2  = (const float*)d_in[11];
    const float* bf2  = (const float*)d_in[12];
    const float* ln2g = (const float*)d_in[13];
    const float* ln2b = (const float*)d_in[14];
    const float* lnfg = (const float*)d_in[15];
    const float* lnfb = (const float*)d_in[16];
    const float* Wout = (const float*)d_in[17];
    const float* bout = (const float*)d_in[18];
    float* out = (float*)d_out;

    float *xe, *q, *k, *v, *sc, *y, *t1, *t2, *ff;
    float *cwq, *cwk, *cwv, *cwu, *cwf1, *cwf2, *cwo;
    cudaGetSymbolAddress((void**)&xe, g_xe);
    cudaGetSymbolAddress((void**)&q,  g_q);
    cudaGetSymbolAddress((void**)&k,  g_k);
    cudaGetSymbolAddress((void**)&v,  g_v);
    cudaGetSymbolAddress((void**)&sc, g_s);
    cudaGetSymbolAddress((void**)&y,  g_y);
    cudaGetSymbolAddress((void**)&t1, g_t1);
    cudaGetSymbolAddress((void**)&t2, g_t2);
    cudaGetSymbolAddress((void**)&ff, g_ff);
    cudaGetSymbolAddress((void**)&cwq,  g_cwq);
    cudaGetSymbolAddress((void**)&cwk,  g_cwk);
    cudaGetSymbolAddress((void**)&cwv,  g_cwv);
    cudaGetSymbolAddress((void**)&cwu,  g_cwu);
    cudaGetSymbolAddress((void**)&cwf1, g_cwf1);
    cudaGetSymbolAddress((void**)&cwf2, g_cwf2);
    cudaGetSymbolAddress((void**)&cwo,  g_cwo);

    const float scale = 1.0f / sqrtf((float)KDIM);

    // weight conversions (tf32-round once)
    cvt(Wq,   cwq,  (size_t)2 * KDIM * KH);
    cvt(Wk,   cwk,  (size_t)2 * KDIM * KH);
    cvt(Wv,   cwv,  (size_t)2 * KDIM * KH);
    cvt(Wu,   cwu,  (size_t)2 * KH * KDIM);
    cvt(Wf1,  cwf1, (size_t)2 * KDIM * FFD);
    cvt(Wf2,  cwf2, (size_t)2 * FFD * KDIM);
    cvt(Wout, cwo,  (size_t)KDIM * VOCAB);

    embed_k<<<BT, 256>>>(x, emb, xe);

    for (int l = 0; l < 2; l++) {
        const float* wq = cwq + (size_t)l * KDIM * KH;
        const float* wk = cwk + (size_t)l * KDIM * KH;
        const float* wv = cwv + (size_t)l * KDIM * KH;
        const float* wu = cwu + (size_t)l * KH * KDIM;

        // QKV: [2048,768] x [768,6144]  -> rounded outputs
        launch_gemm<0, true, 256, true>(xe, wq, q, nullptr, BT, KH, KDIM, KDIM, KH, KH,
                                        0, 0, 0, 0, 0, 0, 1, 1, 0.f);
        launch_gemm<0, true, 256, true>(xe, wk, k, nullptr, BT, KH, KDIM, KDIM, KH, KH,
                                        0, 0, 0, 0, 0, 0, 1, 1, 0.f);
        launch_gemm<0, true, 256, true>(xe, wv, v, nullptr, BT, KH, KDIM, KDIM, KH, KH,
                                        0, 0, 0, 0, 0, 0, 1, 1, 0.f);

        // scores = Q K^T * scale  (B gmem [N=s,K=d]); softmax rounds
        launch_gemm<1, false, 256, false>(q, k, sc, nullptr, TSEQ, TSEQ, KDIM, KH, KH, TSEQ,
                                          (long long)TSEQ * KH, KDIM,
                                          (long long)TSEQ * KH, KDIM,
                                          (long long)HEADS * TSEQ * TSEQ,
                                          (long long)TSEQ * TSEQ,
                                          NBATCH * HEADS, HEADS, scale);

        softmax_k<<<NBATCH * HEADS * TSEQ, 256>>>(sc);

        // y = P @ V  (V gmem [K=s,N=d]) -> rounded (feeds Wu)
        launch_gemm<0, true, 128, true>(sc, v, y, nullptr, TSEQ, KDIM, TSEQ, TSEQ, KH, KH,
                                        (long long)HEADS * TSEQ * TSEQ,
                                        (long long)TSEQ * TSEQ,
                                        (long long)TSEQ * KH, KDIM,
                                        (long long)TSEQ * KH, KDIM,
                                        NBATCH * HEADS, HEADS, 0.f);

        // att = y @ Wu + bu  (feeds LN -> LN rounds)
        launch_gemm<2, true, 128, false>(y, wu, t1, bu + l * KDIM, BT, KDIM, KH,
                                         KH, KDIM, KDIM, 0, 0, 0, 0, 0, 0, 1, 1, 0.f);
        ln_k<<<BT, 256>>>(t1, t2, ln1g + l * KDIM, ln1b + l * KDIM);

        // FFN
        launch_gemm<3, true, 256, true>(t2, cwf1 + (size_t)l * KDIM * FFD, ff,
                                        bf1 + l * FFD, BT, FFD, KDIM,
                                        KDIM, FFD, FFD, 0, 0, 0, 0, 0, 0, 1, 1, 0.f);
        launch_gemm<2, true, 128, false>(ff, cwf2 + (size_t)l * FFD * KDIM, t1,
                                         bf2 + l * KDIM, BT, KDIM, FFD,
                                         FFD, KDIM, KDIM, 0, 0, 0, 0, 0, 0, 1, 1, 0.f);
        ln_k<<<BT, 256>>>(t1, xe, ln2g + l * KDIM, ln2b + l * KDIM);
    }

    ln_k<<<BT, 256>>>(xe, t2, lnfg, lnfb);

    // logits = xf @ Wout + bout : [2048,768] x [768,32000]  (final: no rounding)
    launch_gemm<2, true, 256, false>(t2, cwo, out, bout, BT, VOCAB, KDIM,
                                     KDIM, VOCAB, VOCAB, 0, 0, 0, 0, 0, 0, 1, 1, 0.f);
}